// round 1
// baseline (speedup 1.0000x reference)
#include <cuda_runtime.h>
#include <cuda_bf16.h>
#include <mma.h>
#include <cstdint>
#include <cstddef>

using namespace nvcuda;

// Problem dims
#define B_    2
#define T_    2048
#define C_    1024
#define H_    16
#define NH    64
#define MROWS 4096                       // B*T
constexpr size_t SLOT = (size_t)MROWS * C_;   // 4,194,304 elements per scratch slot

// Scratch slots:
// 0:xr 1:xw 2:xk 3:xv 4:xa 5:xg
// 6:r 7:k 8:v 9:w1(->tanh) 10:a1 11:v1 12:g1(->sigmoid)
// 13:w2raw(->w) 14:a2raw 15:v2raw 16:g 17:y 18:z
__device__ float g_scratch[19ull * 4194304ull];

__device__ __forceinline__ float sigm(float x) { return 1.0f / (1.0f + expf(-x)); }

// ---------------------------------------------------------------------------
// K1: token-shift mixing — 6 outputs from one pass over x
// ---------------------------------------------------------------------------
__global__ __launch_bounds__(256) void mix_kernel(
    const float* __restrict__ X,
    const float* __restrict__ tmr, const float* __restrict__ tmw,
    const float* __restrict__ tmk, const float* __restrict__ tmv,
    const float* __restrict__ tma, const float* __restrict__ tmg,
    float* __restrict__ buf)
{
    const int NC4 = C_ / 4;
    int e4 = blockIdx.x * 256 + threadIdx.x;
    if (e4 >= MROWS * NC4) return;
    int m  = e4 / NC4;
    int c4 = e4 - m * NC4;
    int t  = m & (T_ - 1);

    const float4* X4 = reinterpret_cast<const float4*>(X);
    float4 xc = X4[e4];
    float4 xp = make_float4(0.f, 0.f, 0.f, 0.f);
    if (t != 0) xp = X4[e4 - NC4];
    float4 xx = make_float4(xp.x - xc.x, xp.y - xc.y, xp.z - xc.z, xp.w - xc.w);

    float4* out = reinterpret_cast<float4*>(buf);
    const float* tms[6] = {tmr, tmw, tmk, tmv, tma, tmg};
#pragma unroll
    for (int s = 0; s < 6; s++) {
        float4 tm = reinterpret_cast<const float4*>(tms[s])[c4];
        float4 o = make_float4(xc.x + xx.x * tm.x, xc.y + xx.y * tm.y,
                               xc.z + xx.z * tm.z, xc.w + xx.w * tm.w);
        out[(size_t)s * (SLOT / 4) + e4] = o;
    }
}

// ---------------------------------------------------------------------------
// K2: TF32 WMMA GEMM   out[m,n] = sum_k A[m,k] * W[n,k]
// M=4096, N=1024, K=1024. BM=BN=128, BK=16, 256 threads, cp.async double-buffer.
// ---------------------------------------------------------------------------
#define BM 128
#define BN 128
#define BK 16
#define PADK 20
#define KTILES (C_ / BK)   // 64

__device__ __forceinline__ void cp_async16(uint32_t s, const void* g) {
    asm volatile("cp.async.ca.shared.global [%0], [%1], 16;\n" :: "r"(s), "l"(g));
}
__device__ __forceinline__ void cp_commit() { asm volatile("cp.async.commit_group;\n"); }
template <int Nn> __device__ __forceinline__ void cp_wait() {
    asm volatile("cp.async.wait_group %0;\n" :: "n"(Nn));
}

__global__ __launch_bounds__(256) void gemm_tf32_kernel(
    const float* __restrict__ A, const float* __restrict__ W, float* __restrict__ C)
{
    __shared__ float As[2][BM * PADK];
    __shared__ float Bs[2][BN * PADK];

    const int tid = threadIdx.x;
    const int bm = blockIdx.y, bn = blockIdx.x;
    const float* Ab = A + (size_t)bm * BM * C_;
    const float* Wb = W + (size_t)bn * BN * C_;

    auto load_tiles = [&](int buf, int kt) {
        int k0 = kt * BK;
#pragma unroll
        for (int i = 0; i < 2; i++) {
            int f = tid + i * 256;
            int row = f >> 2;
            int cq  = (f & 3) * 4;
            cp_async16((uint32_t)__cvta_generic_to_shared(&As[buf][row * PADK + cq]),
                       Ab + (size_t)row * C_ + k0 + cq);
            cp_async16((uint32_t)__cvta_generic_to_shared(&Bs[buf][row * PADK + cq]),
                       Wb + (size_t)row * C_ + k0 + cq);
        }
    };

    const int warpId = tid >> 5;
    const int wm = warpId & 1;   // 2 warps along M
    const int wn = warpId >> 1;  // 4 warps along N
    const int rw = wm * 64, cw = wn * 32;

    wmma::fragment<wmma::accumulator, 16, 16, 8, float> acc[4][2];
#pragma unroll
    for (int i = 0; i < 4; i++)
#pragma unroll
        for (int j = 0; j < 2; j++) wmma::fill_fragment(acc[i][j], 0.0f);

    load_tiles(0, 0); cp_commit();

    for (int kt = 0; kt < KTILES; ++kt) {
        int cur = kt & 1;
        if (kt + 1 < KTILES) { load_tiles(cur ^ 1, kt + 1); cp_commit(); cp_wait<1>(); }
        else                 { cp_wait<0>(); }
        __syncthreads();

#pragma unroll
        for (int kk = 0; kk < BK; kk += 8) {
            wmma::fragment<wmma::matrix_a, 16, 16, 8, wmma::precision::tf32, wmma::row_major> af[4];
            wmma::fragment<wmma::matrix_b, 16, 16, 8, wmma::precision::tf32, wmma::col_major> bf[2];
#pragma unroll
            for (int i = 0; i < 4; i++) {
                wmma::load_matrix_sync(af[i], &As[cur][(rw + i * 16) * PADK + kk], PADK);
#pragma unroll
                for (int e = 0; e < af[i].num_elements; e++)
                    af[i].x[e] = wmma::__float_to_tf32(af[i].x[e]);
            }
#pragma unroll
            for (int j = 0; j < 2; j++) {
                wmma::load_matrix_sync(bf[j], &Bs[cur][(cw + j * 16) * PADK + kk], PADK);
#pragma unroll
                for (int e = 0; e < bf[j].num_elements; e++)
                    bf[j].x[e] = wmma::__float_to_tf32(bf[j].x[e]);
            }
#pragma unroll
            for (int i = 0; i < 4; i++)
#pragma unroll
                for (int j = 0; j < 2; j++)
                    wmma::mma_sync(acc[i][j], af[i], bf[j], acc[i][j]);
        }
        __syncthreads();
    }

#pragma unroll
    for (int i = 0; i < 4; i++)
#pragma unroll
        for (int j = 0; j < 2; j++)
            wmma::store_matrix_sync(
                C + (size_t)(bm * BM + rw + i * 16) * C_ + bn * BN + cw + j * 16,
                acc[i][j], C_, wmma::mem_row_major);
}

// ---------------------------------------------------------------------------
// K3: stage-1 activations  (w1 = tanh(w1), g1 = sigmoid(g1)), in place
// ---------------------------------------------------------------------------
__global__ __launch_bounds__(256) void ew1_kernel(float* __restrict__ w1, float* __restrict__ g1)
{
    int e4 = blockIdx.x * 256 + threadIdx.x;
    if (e4 >= (int)(SLOT / 4)) return;
    float4* W1v = reinterpret_cast<float4*>(w1);
    float4* G1v = reinterpret_cast<float4*>(g1);
    float4 a = W1v[e4];
    a.x = tanhf(a.x); a.y = tanhf(a.y); a.z = tanhf(a.z); a.w = tanhf(a.w);
    W1v[e4] = a;
    float4 b = G1v[e4];
    b.x = sigm(b.x); b.y = sigm(b.y); b.z = sigm(b.z); b.w = sigm(b.w);
    G1v[e4] = b;
}

// ---------------------------------------------------------------------------
// K5: stage-2 fused elementwise:
//   w = exp(-0.606531 * sigmoid(w0 + w2raw))   (in place over w2raw)
//   a = sigmoid(a0 + a2raw);  k *= 1 + (a-1)*k_a          (in place)
//   vs = sigmoid(v0 + v2raw); v = v + (v_first - v)*vs    (in place)
// ---------------------------------------------------------------------------
__global__ __launch_bounds__(256) void ew2_kernel(
    float* __restrict__ w2, const float* __restrict__ a2, const float* __restrict__ v2,
    float* __restrict__ k, float* __restrict__ v, const float* __restrict__ v_first,
    const float* __restrict__ w0, const float* __restrict__ a0,
    const float* __restrict__ v0, const float* __restrict__ k_a)
{
    const int NC4 = C_ / 4;
    int e4 = blockIdx.x * 256 + threadIdx.x;
    if (e4 >= (int)(SLOT / 4)) return;
    int c4 = e4 % NC4;

    float4 w0v = reinterpret_cast<const float4*>(w0)[c4];
    float4 a0v = reinterpret_cast<const float4*>(a0)[c4];
    float4 v0v = reinterpret_cast<const float4*>(v0)[c4];
    float4 kav = reinterpret_cast<const float4*>(k_a)[c4];

    float4* W2v = reinterpret_cast<float4*>(w2);
    float4* Kv  = reinterpret_cast<float4*>(k);
    float4* Vv  = reinterpret_cast<float4*>(v);
    const float4* A2v = reinterpret_cast<const float4*>(a2);
    const float4* V2v = reinterpret_cast<const float4*>(v2);
    const float4* VFv = reinterpret_cast<const float4*>(v_first);

    float4 wr = W2v[e4];
    wr.x = expf(-0.606531f * sigm(w0v.x + wr.x));
    wr.y = expf(-0.606531f * sigm(w0v.y + wr.y));
    wr.z = expf(-0.606531f * sigm(w0v.z + wr.z));
    wr.w = expf(-0.606531f * sigm(w0v.w + wr.w));
    W2v[e4] = wr;

    float4 ar = A2v[e4];
    float ax = sigm(a0v.x + ar.x), ay = sigm(a0v.y + ar.y);
    float az = sigm(a0v.z + ar.z), aw = sigm(a0v.w + ar.w);
    float4 kv = Kv[e4];
    kv.x *= 1.0f + (ax - 1.0f) * kav.x;
    kv.y *= 1.0f + (ay - 1.0f) * kav.y;
    kv.z *= 1.0f + (az - 1.0f) * kav.z;
    kv.w *= 1.0f + (aw - 1.0f) * kav.w;
    Kv[e4] = kv;

    float4 vr = V2v[e4];
    float sx = sigm(v0v.x + vr.x), sy = sigm(v0v.y + vr.y);
    float sz = sigm(v0v.z + vr.z), sw = sigm(v0v.w + vr.w);
    float4 vv = Vv[e4];
    float4 vf = VFv[e4];
    vv.x += (vf.x - vv.x) * sx;
    vv.y += (vf.y - vv.y) * sy;
    vv.z += (vf.z - vv.z) * sz;
    vv.w += (vf.w - vv.w) * sw;
    Vv[e4] = vv;
}

// ---------------------------------------------------------------------------
// K6: WKV-7 scan. state[i,j] = state[i,j]*w[i] + k[i]*v[j]; y[i] = sum_j state[i,j]*r[j]
// One warp per (b, h, 8-row group): lane = (row_local*4 + jquarter).
// Each thread: 16 state registers (its 16 j-columns of its row).
// Depth-4 software pipeline of global prefetch to hide L2 latency.
// ---------------------------------------------------------------------------
__global__ __launch_bounds__(32) void wkv_kernel(
    const float* __restrict__ R, const float* __restrict__ Wd,
    const float* __restrict__ K, const float* __restrict__ V, float* __restrict__ Y)
{
    const int bh = blockIdx.x >> 3;       // 0..31  (b*H + h)
    const int rg = blockIdx.x & 7;        // row group
    const int b  = bh >> 4;
    const int h  = bh & 15;
    const int lane = threadIdx.x;
    const int i  = rg * 8 + (lane >> 2);  // state row (k/w/out channel)
    const int jq = lane & 3;              // j-quarter (16 cols)
    const size_t base = ((size_t)b * T_) * C_ + (size_t)h * NH;

    float S[16];
#pragma unroll
    for (int u = 0; u < 16; u++) S[u] = 0.0f;

    float4 rb[4][4], vb[4][4];
    float  wb[4], kb[4];

#pragma unroll
    for (int p = 0; p < 4; p++) {
        size_t q = base + (size_t)p * C_;
        const float4* r4 = reinterpret_cast<const float4*>(R + q + jq * 16);
        const float4* v4 = reinterpret_cast<const float4*>(V + q + jq * 16);
#pragma unroll
        for (int u = 0; u < 4; u++) { rb[p][u] = r4[u]; vb[p][u] = v4[u]; }
        wb[p] = Wd[q + i];
        kb[p] = K[q + i];
    }

#pragma unroll 4
    for (int t = 0; t < T_; t++) {
        const int s = t & 3;
        const float wi = wb[s], ki = kb[s];
        float acc0 = 0.f, acc1 = 0.f, acc2 = 0.f, acc3 = 0.f;
#pragma unroll
        for (int u = 0; u < 4; u++) {
            float4 rv = rb[s][u], vv = vb[s][u];
            float t0 = S[4*u+0] * wi + ki * vv.x; S[4*u+0] = t0; acc0 += t0 * rv.x;
            float t1 = S[4*u+1] * wi + ki * vv.y; S[4*u+1] = t1; acc1 += t1 * rv.y;
            float t2 = S[4*u+2] * wi + ki * vv.z; S[4*u+2] = t2; acc2 += t2 * rv.z;
            float t3 = S[4*u+3] * wi + ki * vv.w; S[4*u+3] = t3; acc3 += t3 * rv.w;
        }
        float sum = (acc0 + acc1) + (acc2 + acc3);
        sum += __shfl_xor_sync(0xffffffffu, sum, 1);
        sum += __shfl_xor_sync(0xffffffffu, sum, 2);
        if (jq == 0) Y[base + (size_t)t * C_ + i] = sum;

        if (t + 4 < T_) {
            size_t q = base + (size_t)(t + 4) * C_;
            const float4* r4 = reinterpret_cast<const float4*>(R + q + jq * 16);
            const float4* v4 = reinterpret_cast<const float4*>(V + q + jq * 16);
#pragma unroll
            for (int u = 0; u < 4; u++) { rb[s][u] = r4[u]; vb[s][u] = v4[u]; }
            wb[s] = Wd[q + i];
            kb[s] = K[q + i];
        }
    }
}

// ---------------------------------------------------------------------------
// K7: LayerNorm(C) + rkv residual + gate:  z = (LN(y) + rkv) * g
//   rkv[c] = (sum_n r[h,n]*k[h,n]*r_k[h,n]) * v[c],  h = c/64
// ---------------------------------------------------------------------------
__global__ __launch_bounds__(256) void ln_gate_kernel(
    const float* __restrict__ Yb, const float* __restrict__ Rb, const float* __restrict__ Kb,
    const float* __restrict__ Vb, const float* __restrict__ Gb,
    const float* __restrict__ rk, const float* __restrict__ lng, const float* __restrict__ lnb,
    float* __restrict__ Zb)
{
    const int m = blockIdx.x;
    const size_t base = (size_t)m * C_;
    __shared__ float sprod[C_];
    __shared__ float hdot[H_];
    __shared__ float rs[8], rq[8], stats[2];

    const int tid = threadIdx.x;
    float yv[4];
    float lsum = 0.f, lsq = 0.f;
#pragma unroll
    for (int u = 0; u < 4; u++) {
        int c = tid + u * 256;
        float t = Yb[base + c];
        yv[u] = t; lsum += t; lsq += t * t;
        sprod[c] = Rb[base + c] * Kb[base + c] * rk[c];
    }
#pragma unroll
    for (int o = 16; o > 0; o >>= 1) {
        lsum += __shfl_xor_sync(0xffffffffu, lsum, o);
        lsq  += __shfl_xor_sync(0xffffffffu, lsq,  o);
    }
    if ((tid & 31) == 0) { rs[tid >> 5] = lsum; rq[tid >> 5] = lsq; }
    __syncthreads();
    if (tid == 0) {
        float s = 0.f, q = 0.f;
        for (int wq = 0; wq < 8; wq++) { s += rs[wq]; q += rq[wq]; }
        float mu = s / (float)C_;
        stats[0] = mu;
        stats[1] = rsqrtf(q / (float)C_ - mu * mu + 1e-5f);
    }
    if (tid < 16) {
        float d = 0.f;
        for (int n = 0; n < 64; n++) d += sprod[tid * 64 + n];
        hdot[tid] = d;
    }
    __syncthreads();
    const float mu = stats[0], rstd = stats[1];
#pragma unroll
    for (int u = 0; u < 4; u++) {
        int c = tid + u * 256;
        int hh = c >> 6;
        float z = ((yv[u] - mu) * rstd * lng[c] + lnb[c] + hdot[hh] * Vb[base + c]) * Gb[base + c];
        Zb[base + c] = z;
    }
}

// ---------------------------------------------------------------------------
// Launcher
// ---------------------------------------------------------------------------
extern "C" void kernel_launch(void* const* d_in, const int* in_sizes, int n_in,
                              void* d_out, int out_size)
{
    (void)in_sizes; (void)n_in; (void)out_size;
    const float* x       = (const float*)d_in[0];
    const float* v_first = (const float*)d_in[1];
    const float* Wr  = (const float*)d_in[2];
    const float* Wk  = (const float*)d_in[3];
    const float* Wv  = (const float*)d_in[4];
    const float* Wo  = (const float*)d_in[5];
    const float* Wg1 = (const float*)d_in[6];
    const float* Wg2 = (const float*)d_in[7];
    const float* W1  = (const float*)d_in[8];
    const float* W2  = (const float*)d_in[9];
    const float* A1  = (const float*)d_in[10];
    const float* A2  = (const float*)d_in[11];
    const float* V1  = (const float*)d_in[12];
    const float* V2  = (const float*)d_in[13];
    const float* tm_r = (const float*)d_in[14];
    const float* tm_w = (const float*)d_in[15];
    const float* tm_k = (const float*)d_in[16];
    const float* tm_v = (const float*)d_in[17];
    const float* tm_a = (const float*)d_in[18];
    const float* tm_g = (const float*)d_in[19];
    const float* w0  = (const float*)d_in[20];
    const float* a0  = (const float*)d_in[21];
    const float* v0  = (const float*)d_in[22];
    // d_in[23] = k_k (unused by the reference)
    const float* k_a = (const float*)d_in[24];
    const float* r_k = (const float*)d_in[25];
    const float* ln_g = (const float*)d_in[26];
    const float* ln_b = (const float*)d_in[27];

    float* buf = nullptr;
    cudaGetSymbolAddress((void**)&buf, g_scratch);
    auto S = [&](int s) { return buf + (size_t)s * SLOT; };

    const int MC4 = MROWS * C_ / 4;          // 1,048,576
    const int EW_BLOCKS = MC4 / 256;         // 4096
    dim3 gg(C_ / BN, MROWS / BM);            // (8, 32)

    // K1: token-shift mixes -> slots 0..5 (xr,xw,xk,xv,xa,xg)
    mix_kernel<<<EW_BLOCKS, 256>>>(x, tm_r, tm_w, tm_k, tm_v, tm_a, tm_g, buf);

    // Stage-1 GEMMs
    gemm_tf32_kernel<<<gg, 256>>>(S(0), Wr,  S(6));   // r
    gemm_tf32_kernel<<<gg, 256>>>(S(2), Wk,  S(7));   // k
    gemm_tf32_kernel<<<gg, 256>>>(S(3), Wv,  S(8));   // v
    gemm_tf32_kernel<<<gg, 256>>>(S(1), W1,  S(9));   // w1
    gemm_tf32_kernel<<<gg, 256>>>(S(4), A1,  S(10));  // a1
    gemm_tf32_kernel<<<gg, 256>>>(S(3), V1,  S(11));  // v1
    gemm_tf32_kernel<<<gg, 256>>>(S(5), Wg1, S(12));  // g1

    // K3: tanh(w1), sigmoid(g1)
    ew1_kernel<<<EW_BLOCKS, 256>>>(S(9), S(12));

    // Stage-2 GEMMs
    gemm_tf32_kernel<<<gg, 256>>>(S(9),  W2,  S(13)); // w2raw
    gemm_tf32_kernel<<<gg, 256>>>(S(10), A2,  S(14)); // a2raw
    gemm_tf32_kernel<<<gg, 256>>>(S(11), V2,  S(15)); // v2raw
    gemm_tf32_kernel<<<gg, 256>>>(S(12), Wg2, S(16)); // g

    // K5: w decay, k adjust, v blend
    ew2_kernel<<<EW_BLOCKS, 256>>>(S(13), S(14), S(15), S(7), S(8), v_first,
                                   w0, a0, v0, k_a);

    // K6: WKV scan -> y (slot 17)
    wkv_kernel<<<256, 32>>>(S(6), S(13), S(7), S(8), S(17));

    // K7: LN + rkv + gate -> z (slot 18)
    ln_gate_kernel<<<MROWS, 256>>>(S(17), S(6), S(7), S(8), S(16),
                                   r_k, ln_g, ln_b, S(18));

    // Final GEMM: out = z @ Wo^T
    gemm_tf32_kernel<<<gg, 256>>>(S(18), Wo, (float*)d_out);
}

// round 2
// speedup vs baseline: 1.2022x; 1.2022x over previous
#include <cuda_runtime.h>
#include <cuda_bf16.h>
#include <mma.h>
#include <cstdint>
#include <cstddef>

using namespace nvcuda;

// Problem dims
#define B_    2
#define T_    2048
#define C_    1024
#define H_    16
#define NH    64
#define MROWS 4096                       // B*T
constexpr size_t SLOT = (size_t)MROWS * C_;   // 4,194,304 elements per scratch slot
constexpr size_t WSLOT = (size_t)C_ * C_;     // 1,048,576 elements per weight

// Scratch slots:
// 0:xr 1:xw 2:xk 3:xv 4:xa 5:xg
// 6:r 7:k 8:v 9:w1(tanh'd) 10:a1 11:v1 12:g1(sigmoid'd)
// 13:w2raw(->w) 14:a2raw 15:v2raw 16:g 17:y 18:z
// then 12 tf32-rounded weight copies
__device__ float g_scratch[19ull * 4194304ull + 12ull * 1048576ull];

__device__ __forceinline__ float sigm(float x) { return 1.0f / (1.0f + expf(-x)); }
__device__ __forceinline__ float rtf(float x) { return wmma::__float_to_tf32(x); }
__device__ __forceinline__ float4 rtf4(float4 v) {
    return make_float4(rtf(v.x), rtf(v.y), rtf(v.z), rtf(v.w));
}

// ---------------------------------------------------------------------------
// K0: one-time tf32 rounding of the 12 weight matrices
// ---------------------------------------------------------------------------
struct Ptr12 { const float* p[12]; };

__global__ __launch_bounds__(256) void wcvt_kernel(Ptr12 ws, float* __restrict__ out)
{
    int w  = blockIdx.y;
    int e4 = blockIdx.x * 256 + threadIdx.x;   // 0..262143
    float4 v = reinterpret_cast<const float4*>(ws.p[w])[e4];
    reinterpret_cast<float4*>(out + (size_t)w * WSLOT)[e4] = rtf4(v);
}

// ---------------------------------------------------------------------------
// K1: token-shift mixing — 6 tf32-rounded outputs from one pass over x
// ---------------------------------------------------------------------------
__global__ __launch_bounds__(256) void mix_kernel(
    const float* __restrict__ X,
    const float* __restrict__ tmr, const float* __restrict__ tmw,
    const float* __restrict__ tmk, const float* __restrict__ tmv,
    const float* __restrict__ tma, const float* __restrict__ tmg,
    float* __restrict__ buf)
{
    const int NC4 = C_ / 4;
    int e4 = blockIdx.x * 256 + threadIdx.x;
    if (e4 >= MROWS * NC4) return;
    int m  = e4 / NC4;
    int c4 = e4 - m * NC4;
    int t  = m & (T_ - 1);

    const float4* X4 = reinterpret_cast<const float4*>(X);
    float4 xc = X4[e4];
    float4 xp = make_float4(0.f, 0.f, 0.f, 0.f);
    if (t != 0) xp = X4[e4 - NC4];
    float4 xx = make_float4(xp.x - xc.x, xp.y - xc.y, xp.z - xc.z, xp.w - xc.w);

    float4* out = reinterpret_cast<float4*>(buf);
    const float* tms[6] = {tmr, tmw, tmk, tmv, tma, tmg};
#pragma unroll
    for (int s = 0; s < 6; s++) {
        float4 tm = reinterpret_cast<const float4*>(tms[s])[c4];
        float4 o = make_float4(xc.x + xx.x * tm.x, xc.y + xx.y * tm.y,
                               xc.z + xx.z * tm.z, xc.w + xx.w * tm.w);
        out[(size_t)s * (SLOT / 4) + e4] = rtf4(o);
    }
}

// ---------------------------------------------------------------------------
// K2: batched TF32 WMMA GEMM   out[m,n] = sum_k A[m,k] * W[n,k]
// Inputs are pre-rounded to tf32 (no in-loop conversion). 4-stage cp.async,
// BM=BN=128, BK=16, 256 threads, 2 CTAs/SM. blockIdx.z selects the GEMM.
// Epilogue activations: 0 none, 1 tanh+round, 2 sigmoid+round, 3 round.
// ---------------------------------------------------------------------------
#define BM 128
#define BN 128
#define BK 16
#define PADK 20
#define KTILES (C_ / BK)   // 64
#define STAGES 4
#define ASZ (128 * PADK)   // floats per matrix per stage
constexpr int GEMM_SMEM = STAGES * 2 * ASZ * 4;   // 81920 bytes

struct GemmItem { const float* A; const float* W; float* O; int act; };
struct GemmBatch7 { GemmItem it[7]; };

__device__ __forceinline__ void cp_async16(uint32_t s, const void* g) {
    asm volatile("cp.async.ca.shared.global [%0], [%1], 16;\n" :: "r"(s), "l"(g));
}
__device__ __forceinline__ void cp_commit() { asm volatile("cp.async.commit_group;\n"); }
template <int Nn> __device__ __forceinline__ void cp_wait() {
    asm volatile("cp.async.wait_group %0;\n" :: "n"(Nn));
}

extern __shared__ float smem_g[];

__global__ __launch_bounds__(256, 2) void gemm_batch_kernel(GemmBatch7 bt)
{
    const GemmItem gi = bt.it[blockIdx.z];
    float* As = smem_g;
    float* Bs = smem_g + STAGES * ASZ;

    const int tid = threadIdx.x;
    const int bm = blockIdx.y, bn = blockIdx.x;
    const float* Ab = gi.A + (size_t)bm * BM * C_;
    const float* Wb = gi.W + (size_t)bn * BN * C_;

    auto load_tiles = [&](int buf, int kt) {
        int k0 = kt * BK;
        float* Asb = As + buf * ASZ;
        float* Bsb = Bs + buf * ASZ;
#pragma unroll
        for (int i2 = 0; i2 < 2; i2++) {
            int f = tid + i2 * 256;
            int row = f >> 2;
            int cq  = (f & 3) * 4;
            cp_async16((uint32_t)__cvta_generic_to_shared(&Asb[row * PADK + cq]),
                       Ab + (size_t)row * C_ + k0 + cq);
            cp_async16((uint32_t)__cvta_generic_to_shared(&Bsb[row * PADK + cq]),
                       Wb + (size_t)row * C_ + k0 + cq);
        }
    };

    const int warpId = tid >> 5;
    const int wm = warpId & 1;   // 2 warps along M
    const int wn = warpId >> 1;  // 4 warps along N
    const int rw = wm * 64, cw = wn * 32;

    wmma::fragment<wmma::accumulator, 16, 16, 8, float> acc[4][2];
#pragma unroll
    for (int i = 0; i < 4; i++)
#pragma unroll
        for (int j = 0; j < 2; j++) wmma::fill_fragment(acc[i][j], 0.0f);

    int load_kt = 0;
#pragma unroll
    for (int s = 0; s < STAGES - 1; s++) {
        load_tiles(s, load_kt); cp_commit(); load_kt++;
    }

    for (int kt = 0; kt < KTILES; ++kt) {
        cp_wait<STAGES - 2>();
        __syncthreads();
        if (load_kt < KTILES) load_tiles(load_kt & (STAGES - 1), load_kt);
        cp_commit(); load_kt++;

        const float* Asb = As + (kt & (STAGES - 1)) * ASZ;
        const float* Bsb = Bs + (kt & (STAGES - 1)) * ASZ;

#pragma unroll
        for (int kk = 0; kk < BK; kk += 8) {
            wmma::fragment<wmma::matrix_a, 16, 16, 8, wmma::precision::tf32, wmma::row_major> af[4];
            wmma::fragment<wmma::matrix_b, 16, 16, 8, wmma::precision::tf32, wmma::col_major> bf[2];
#pragma unroll
            for (int i = 0; i < 4; i++)
                wmma::load_matrix_sync(af[i], &Asb[(rw + i * 16) * PADK + kk], PADK);
#pragma unroll
            for (int j = 0; j < 2; j++)
                wmma::load_matrix_sync(bf[j], &Bsb[(cw + j * 16) * PADK + kk], PADK);
#pragma unroll
            for (int i = 0; i < 4; i++)
#pragma unroll
                for (int j = 0; j < 2; j++)
                    wmma::mma_sync(acc[i][j], af[i], bf[j], acc[i][j]);
        }
    }

    const int act = gi.act;
#pragma unroll
    for (int i = 0; i < 4; i++)
#pragma unroll
        for (int j = 0; j < 2; j++) {
            if (act == 1) {
#pragma unroll
                for (int e = 0; e < acc[i][j].num_elements; e++)
                    acc[i][j].x[e] = rtf(tanhf(acc[i][j].x[e]));
            } else if (act == 2) {
#pragma unroll
                for (int e = 0; e < acc[i][j].num_elements; e++)
                    acc[i][j].x[e] = rtf(sigm(acc[i][j].x[e]));
            } else if (act == 3) {
#pragma unroll
                for (int e = 0; e < acc[i][j].num_elements; e++)
                    acc[i][j].x[e] = rtf(acc[i][j].x[e]);
            }
            wmma::store_matrix_sync(
                gi.O + (size_t)(bm * BM + rw + i * 16) * C_ + bn * BN + cw + j * 16,
                acc[i][j], C_, wmma::mem_row_major);
        }
}

// ---------------------------------------------------------------------------
// K5: stage-2 fused elementwise (w decay / k adjust / v blend), in place
// ---------------------------------------------------------------------------
__global__ __launch_bounds__(256) void ew2_kernel(
    float* __restrict__ w2, const float* __restrict__ a2, const float* __restrict__ v2,
    float* __restrict__ k, float* __restrict__ v, const float* __restrict__ v_first,
    const float* __restrict__ w0, const float* __restrict__ a0,
    const float* __restrict__ v0, const float* __restrict__ k_a)
{
    const int NC4 = C_ / 4;
    int e4 = blockIdx.x * 256 + threadIdx.x;
    if (e4 >= (int)(SLOT / 4)) return;
    int c4 = e4 % NC4;

    float4 w0v = reinterpret_cast<const float4*>(w0)[c4];
    float4 a0v = reinterpret_cast<const float4*>(a0)[c4];
    float4 v0v = reinterpret_cast<const float4*>(v0)[c4];
    float4 kav = reinterpret_cast<const float4*>(k_a)[c4];

    float4* W2v = reinterpret_cast<float4*>(w2);
    float4* Kv  = reinterpret_cast<float4*>(k);
    float4* Vv  = reinterpret_cast<float4*>(v);
    const float4* A2v = reinterpret_cast<const float4*>(a2);
    const float4* V2v = reinterpret_cast<const float4*>(v2);
    const float4* VFv = reinterpret_cast<const float4*>(v_first);

    float4 wr = W2v[e4];
    wr.x = expf(-0.606531f * sigm(w0v.x + wr.x));
    wr.y = expf(-0.606531f * sigm(w0v.y + wr.y));
    wr.z = expf(-0.606531f * sigm(w0v.z + wr.z));
    wr.w = expf(-0.606531f * sigm(w0v.w + wr.w));
    W2v[e4] = wr;

    float4 ar = A2v[e4];
    float ax = sigm(a0v.x + ar.x), ay = sigm(a0v.y + ar.y);
    float az = sigm(a0v.z + ar.z), aw = sigm(a0v.w + ar.w);
    float4 kv = Kv[e4];
    kv.x *= 1.0f + (ax - 1.0f) * kav.x;
    kv.y *= 1.0f + (ay - 1.0f) * kav.y;
    kv.z *= 1.0f + (az - 1.0f) * kav.z;
    kv.w *= 1.0f + (aw - 1.0f) * kav.w;
    Kv[e4] = kv;

    float4 vr = V2v[e4];
    float sx = sigm(v0v.x + vr.x), sy = sigm(v0v.y + vr.y);
    float sz = sigm(v0v.z + vr.z), sw = sigm(v0v.w + vr.w);
    float4 vv = Vv[e4];
    float4 vf = VFv[e4];
    vv.x += (vf.x - vv.x) * sx;
    vv.y += (vf.y - vv.y) * sy;
    vv.z += (vf.z - vv.z) * sz;
    vv.w += (vf.w - vv.w) * sw;
    Vv[e4] = vv;
}

// ---------------------------------------------------------------------------
// K6: WKV-7 scan. state[i,j] = state[i,j]*w[i] + k[i]*v[j]; y[i] = sum_j state[i,j]*r[j]
// One warp per (b, h, 4-row group): lane = row_local*8 + jq (8 j-cols each).
// S[8] per thread. Depth-4 prefetch; y-reduction batched every 4 steps so the
// 4 shuffle trees pipeline.
// ---------------------------------------------------------------------------
__global__ __launch_bounds__(32) void wkv_kernel(
    const float* __restrict__ R, const float* __restrict__ Wd,
    const float* __restrict__ K, const float* __restrict__ V, float* __restrict__ Y)
{
    const int bh = blockIdx.x >> 4;       // 0..31  (b*H + h)
    const int rg = blockIdx.x & 15;       // row group (4 rows each)
    const int b  = bh >> 4;
    const int h  = bh & 15;
    const int lane = threadIdx.x;
    const int i  = rg * 4 + (lane >> 3);  // state row (k/w/out channel)
    const int jq = lane & 7;              // j-octant (8 cols)
    const size_t base = ((size_t)b * T_) * C_ + (size_t)h * NH;

    float S[8];
#pragma unroll
    for (int u = 0; u < 8; u++) S[u] = 0.0f;

    float4 rb[4][2], vb[4][2];
    float  wb[4], kb[4];

#pragma unroll
    for (int p = 0; p < 4; p++) {
        size_t q = base + (size_t)p * C_;
        const float4* r4 = reinterpret_cast<const float4*>(R + q + jq * 8);
        const float4* v4 = reinterpret_cast<const float4*>(V + q + jq * 8);
        rb[p][0] = r4[0]; rb[p][1] = r4[1];
        vb[p][0] = v4[0]; vb[p][1] = v4[1];
        wb[p] = Wd[q + i];
        kb[p] = K[q + i];
    }

    float yacc[4];

    for (int t0 = 0; t0 < T_; t0 += 4) {
#pragma unroll
        for (int s = 0; s < 4; s++) {
            const float wi = wb[s], ki = kb[s];
            float a0 = 0.f, a1 = 0.f;
            {
                float4 rv = rb[s][0], vv = vb[s][0];
                float t0v = S[0] * wi + ki * vv.x; S[0] = t0v; a0 += t0v * rv.x;
                float t1v = S[1] * wi + ki * vv.y; S[1] = t1v; a1 += t1v * rv.y;
                float t2v = S[2] * wi + ki * vv.z; S[2] = t2v; a0 += t2v * rv.z;
                float t3v = S[3] * wi + ki * vv.w; S[3] = t3v; a1 += t3v * rv.w;
            }
            {
                float4 rv = rb[s][1], vv = vb[s][1];
                float t0v = S[4] * wi + ki * vv.x; S[4] = t0v; a0 += t0v * rv.x;
                float t1v = S[5] * wi + ki * vv.y; S[5] = t1v; a1 += t1v * rv.y;
                float t2v = S[6] * wi + ki * vv.z; S[6] = t2v; a0 += t2v * rv.z;
                float t3v = S[7] * wi + ki * vv.w; S[7] = t3v; a1 += t3v * rv.w;
            }
            yacc[s] = a0 + a1;

            int tn = t0 + s + 4;
            if (tn < T_) {
                size_t q = base + (size_t)tn * C_;
                const float4* r4 = reinterpret_cast<const float4*>(R + q + jq * 8);
                const float4* v4 = reinterpret_cast<const float4*>(V + q + jq * 8);
                rb[s][0] = r4[0]; rb[s][1] = r4[1];
                vb[s][0] = v4[0]; vb[s][1] = v4[1];
                wb[s] = Wd[q + i];
                kb[s] = K[q + i];
            }
        }
#pragma unroll
        for (int s = 0; s < 4; s++) {
            float red = yacc[s];
            red += __shfl_xor_sync(0xffffffffu, red, 1);
            red += __shfl_xor_sync(0xffffffffu, red, 2);
            red += __shfl_xor_sync(0xffffffffu, red, 4);
            if (jq == 0) Y[base + (size_t)(t0 + s) * C_ + i] = red;
        }
    }
}

// ---------------------------------------------------------------------------
// K7: LayerNorm(C) + rkv residual + gate:  z = (LN(y) + rkv) * g   (tf32 out)
// ---------------------------------------------------------------------------
__global__ __launch_bounds__(256) void ln_gate_kernel(
    const float* __restrict__ Yb, const float* __restrict__ Rb, const float* __restrict__ Kb,
    const float* __restrict__ Vb, const float* __restrict__ Gb,
    const float* __restrict__ rk, const float* __restrict__ lng, const float* __restrict__ lnb,
    float* __restrict__ Zb)
{
    const int m = blockIdx.x;
    const size_t base = (size_t)m * C_;
    __shared__ float sprod[C_];
    __shared__ float hdot[H_];
    __shared__ float rs[8], rq[8], stats[2];

    const int tid = threadIdx.x;
    float yv[4];
    float lsum = 0.f, lsq = 0.f;
#pragma unroll
    for (int u = 0; u < 4; u++) {
        int c = tid + u * 256;
        float t = Yb[base + c];
        yv[u] = t; lsum += t; lsq += t * t;
        sprod[c] = Rb[base + c] * Kb[base + c] * rk[c];
    }
#pragma unroll
    for (int o = 16; o > 0; o >>= 1) {
        lsum += __shfl_xor_sync(0xffffffffu, lsum, o);
        lsq  += __shfl_xor_sync(0xffffffffu, lsq,  o);
    }
    if ((tid & 31) == 0) { rs[tid >> 5] = lsum; rq[tid >> 5] = lsq; }
    __syncthreads();
    if (tid == 0) {
        float s = 0.f, q = 0.f;
        for (int wq = 0; wq < 8; wq++) { s += rs[wq]; q += rq[wq]; }
        float mu = s / (float)C_;
        stats[0] = mu;
        stats[1] = rsqrtf(q / (float)C_ - mu * mu + 1e-5f);
    }
    if (tid < 16) {
        float d = 0.f;
        for (int n = 0; n < 64; n++) d += sprod[tid * 64 + n];
        hdot[tid] = d;
    }
    __syncthreads();
    const float mu = stats[0], rstd = stats[1];
#pragma unroll
    for (int u = 0; u < 4; u++) {
        int c = tid + u * 256;
        int hh = c >> 6;
        float z = ((yv[u] - mu) * rstd * lng[c] + lnb[c] + hdot[hh] * Vb[base + c]) * Gb[base + c];
        Zb[base + c] = rtf(z);
    }
}

// ---------------------------------------------------------------------------
// Launcher
// ---------------------------------------------------------------------------
extern "C" void kernel_launch(void* const* d_in, const int* in_sizes, int n_in,
                              void* d_out, int out_size)
{
    (void)in_sizes; (void)n_in; (void)out_size;
    const float* x       = (const float*)d_in[0];
    const float* v_first = (const float*)d_in[1];
    const float* Wr  = (const float*)d_in[2];
    const float* Wk  = (const float*)d_in[3];
    const float* Wv  = (const float*)d_in[4];
    const float* Wo  = (const float*)d_in[5];
    const float* Wg1 = (const float*)d_in[6];
    const float* Wg2 = (const float*)d_in[7];
    const float* W1  = (const float*)d_in[8];
    const float* W2  = (const float*)d_in[9];
    const float* A1  = (const float*)d_in[10];
    const float* A2  = (const float*)d_in[11];
    const float* V1  = (const float*)d_in[12];
    const float* V2  = (const float*)d_in[13];
    const float* tm_r = (const float*)d_in[14];
    const float* tm_w = (const float*)d_in[15];
    const float* tm_k = (const float*)d_in[16];
    const float* tm_v = (const float*)d_in[17];
    const float* tm_a = (const float*)d_in[18];
    const float* tm_g = (const float*)d_in[19];
    const float* w0  = (const float*)d_in[20];
    const float* a0  = (const float*)d_in[21];
    const float* v0  = (const float*)d_in[22];
    // d_in[23] = k_k (unused by the reference)
    const float* k_a = (const float*)d_in[24];
    const float* r_k = (const float*)d_in[25];
    const float* ln_g = (const float*)d_in[26];
    const float* ln_b = (const float*)d_in[27];

    float* buf = nullptr;
    cudaGetSymbolAddress((void**)&buf, g_scratch);
    auto S  = [&](int s) { return buf + (size_t)s * SLOT; };
    float* wbase = buf + 19 * SLOT;
    auto WB = [&](int w) { return (const float*)(wbase + (size_t)w * WSLOT); };

    cudaFuncSetAttribute((const void*)gemm_batch_kernel,
                         cudaFuncAttributeMaxDynamicSharedMemorySize, GEMM_SMEM);

    const int MC4 = MROWS * C_ / 4;          // 1,048,576
    const int EW_BLOCKS = MC4 / 256;         // 4096

    // K0: tf32-round the weights
    Ptr12 ws;
    ws.p[0] = Wr;  ws.p[1] = Wk;  ws.p[2] = Wv;  ws.p[3] = W1;
    ws.p[4] = A1;  ws.p[5] = V1;  ws.p[6] = Wg1; ws.p[7] = W2;
    ws.p[8] = A2;  ws.p[9] = V2;  ws.p[10] = Wg2; ws.p[11] = Wo;
    wcvt_kernel<<<dim3(1024, 12), 256>>>(ws, wbase);

    // K1: token-shift mixes -> slots 0..5 (xr,xw,xk,xv,xa,xg), tf32-rounded
    mix_kernel<<<EW_BLOCKS, 256>>>(x, tm_r, tm_w, tm_k, tm_v, tm_a, tm_g, buf);

    // Stage-1 batched GEMMs (7): r,k,v,w1(tanh),a1,v1,g1(sigmoid)
    GemmBatch7 b1;
    b1.it[0] = { S(0), WB(0), S(6),  0 };   // r  = xr @ Wr^T
    b1.it[1] = { S(2), WB(1), S(7),  0 };   // k  = xk @ Wk^T
    b1.it[2] = { S(3), WB(2), S(8),  0 };   // v  = xv @ Wv^T
    b1.it[3] = { S(1), WB(3), S(9),  1 };   // w1 = tanh(xw @ W1^T), tf32
    b1.it[4] = { S(4), WB(4), S(10), 3 };   // a1 = xa @ A1^T, tf32
    b1.it[5] = { S(3), WB(5), S(11), 3 };   // v1 = xv @ V1^T, tf32
    b1.it[6] = { S(5), WB(6), S(12), 2 };   // g1 = sigmoid(xg @ Wg1^T), tf32
    gemm_batch_kernel<<<dim3(C_ / BN, MROWS / BM, 7), 256, GEMM_SMEM>>>(b1);

    // Stage-2 batched GEMMs (4): w2raw, a2raw, v2raw, g
    GemmBatch7 b2;
    b2.it[0] = { S(9),  WB(7),  S(13), 0 };
    b2.it[1] = { S(10), WB(8),  S(14), 0 };
    b2.it[2] = { S(11), WB(9),  S(15), 0 };
    b2.it[3] = { S(12), WB(10), S(16), 0 };
    gemm_batch_kernel<<<dim3(C_ / BN, MROWS / BM, 4), 256, GEMM_SMEM>>>(b2);

    // K5: w decay, k adjust, v blend
    ew2_kernel<<<EW_BLOCKS, 256>>>(S(13), S(14), S(15), S(7), S(8), v_first,
                                   w0, a0, v0, k_a);

    // K6: WKV scan -> y (slot 17)
    wkv_kernel<<<512, 32>>>(S(6), S(13), S(7), S(8), S(17));

    // K7: LN + rkv + gate -> z (slot 18), tf32-rounded
    ln_gate_kernel<<<MROWS, 256>>>(S(17), S(6), S(7), S(8), S(16),
                                   r_k, ln_g, ln_b, S(18));

    // Final GEMM: out = z @ Wo^T
    GemmBatch7 b3;
    b3.it[0] = { S(18), WB(11), (float*)d_out, 0 };
    gemm_batch_kernel<<<dim3(C_ / BN, MROWS / BM, 1), 256, GEMM_SMEM>>>(b3);
}

// round 4
// speedup vs baseline: 1.7217x; 1.4322x over previous
#include <cuda_runtime.h>
#include <cuda_bf16.h>
#include <cstdint>
#include <cstddef>

// Problem dims
#define B_    2
#define T_    2048
#define C_    1024
#define H_    16
#define NH    64
#define MROWS 4096                       // B*T
constexpr size_t SLOT = (size_t)MROWS * C_;   // 4,194,304 elements per scratch slot
constexpr size_t WSLOT = (size_t)C_ * C_;     // 1,048,576 elements per weight

// Scratch slots:
// 0:xr 1:xw 2:xk 3:xv 4:xa 5:xg
// 6:r 7:k 8:v 9:w1(tanh'd) 10:a1 11:v1 12:g1(sigmoid'd)
// 13:w2raw(->w) 14:a2raw 15:v2raw 16:g 17:y 18:z
// then 12 tf32-rounded weight copies
__device__ float g_scratch[19ull * 4194304ull + 12ull * 1048576ull];

__device__ __forceinline__ float sigm(float x) { return 1.0f / (1.0f + expf(-x)); }
__device__ __forceinline__ float rtf(float x) {
    float r; asm("cvt.rna.tf32.f32 %0, %1;" : "=f"(r) : "f"(x)); return r;
}
__device__ __forceinline__ float4 rtf4(float4 v) {
    return make_float4(rtf(v.x), rtf(v.y), rtf(v.z), rtf(v.w));
}

__device__ __forceinline__ uint32_t smem_u32(const void* p) {
    uint32_t a;
    asm("{ .reg .u64 t; cvta.to.shared.u64 t, %1; cvt.u32.u64 %0, t; }" : "=r"(a) : "l"(p));
    return a;
}
__device__ __forceinline__ void cp_async16(uint32_t s, const void* g) {
    asm volatile("cp.async.ca.shared.global [%0], [%1], 16;\n" :: "r"(s), "l"(g));
}
__device__ __forceinline__ void cp_commit() { asm volatile("cp.async.commit_group;\n"); }
template <int Nn> __device__ __forceinline__ void cp_wait() {
    asm volatile("cp.async.wait_group %0;\n" :: "n"(Nn));
}

// ---------------------------------------------------------------------------
// K0: one-time tf32 rounding of the 12 weight matrices
// ---------------------------------------------------------------------------
struct Ptr12 { const float* p[12]; };

__global__ __launch_bounds__(256) void wcvt_kernel(Ptr12 ws, float* __restrict__ out)
{
    int w  = blockIdx.y;
    int e4 = blockIdx.x * 256 + threadIdx.x;   // 0..262143
    float4 v = reinterpret_cast<const float4*>(ws.p[w])[e4];
    reinterpret_cast<float4*>(out + (size_t)w * WSLOT)[e4] = rtf4(v);
}

// ---------------------------------------------------------------------------
// K1: token-shift mixing — 6 tf32-rounded outputs from one pass over x
// ---------------------------------------------------------------------------
__global__ __launch_bounds__(256) void mix_kernel(
    const float* __restrict__ X,
    const float* __restrict__ tmr, const float* __restrict__ tmw,
    const float* __restrict__ tmk, const float* __restrict__ tmv,
    const float* __restrict__ tma, const float* __restrict__ tmg,
    float* __restrict__ buf)
{
    const int NC4 = C_ / 4;
    int e4 = blockIdx.x * 256 + threadIdx.x;
    if (e4 >= MROWS * NC4) return;
    int m  = e4 / NC4;
    int c4 = e4 - m * NC4;
    int t  = m & (T_ - 1);

    const float4* X4 = reinterpret_cast<const float4*>(X);
    float4 xc = X4[e4];
    float4 xp = make_float4(0.f, 0.f, 0.f, 0.f);
    if (t != 0) xp = X4[e4 - NC4];
    float4 xx = make_float4(xp.x - xc.x, xp.y - xc.y, xp.z - xc.z, xp.w - xc.w);

    float4* out = reinterpret_cast<float4*>(buf);
    const float* tms[6] = {tmr, tmw, tmk, tmv, tma, tmg};
#pragma unroll
    for (int s = 0; s < 6; s++) {
        float4 tm = reinterpret_cast<const float4*>(tms[s])[c4];
        float4 o = make_float4(xc.x + xx.x * tm.x, xc.y + xx.y * tm.y,
                               xc.z + xx.z * tm.z, xc.w + xx.w * tm.w);
        out[(size_t)s * (SLOT / 4) + e4] = rtf4(o);
    }
}

// ---------------------------------------------------------------------------
// K2: hand-rolled TF32 mma GEMM   out[m,n] = sum_k A[m,k] * W[n,k]
// BM=BN=128, BK=32, 3-stage cp.async, 8 warps (2M x 4N), warp tile 64x32,
// register double-buffered fragments. blockIdx.z selects the GEMM.
// Epilogue act: 0 none, 1 tanh+round, 2 sigmoid+round, 3 round.
// ---------------------------------------------------------------------------
#define BMG 128
#define BNG 128
#define BKG 32
#define NKT (C_ / BKG)        // 32
#define RS  36                // padded row stride in floats (32 + 4)
#define AST (128 * RS)        // floats per matrix tile per stage (4608)
#define STF (2 * AST)         // floats per stage (9216)
constexpr int GEMM_SMEM = 3 * STF * 4;   // 110592 bytes

struct GemmItem { const float* A; const float* W; float* O; int act; };
struct GemmBatch7 { GemmItem it[7]; };

#define MMA_TF32(d, a, b) \
    asm volatile( \
        "mma.sync.aligned.m16n8k8.row.col.f32.tf32.tf32.f32 " \
        "{%0,%1,%2,%3}, {%4,%5,%6,%7}, {%8,%9}, {%0,%1,%2,%3};" \
        : "+f"((d)[0]), "+f"((d)[1]), "+f"((d)[2]), "+f"((d)[3]) \
        : "r"((a)[0]), "r"((a)[1]), "r"((a)[2]), "r"((a)[3]), \
          "r"((b)[0]), "r"((b)[1]))

extern __shared__ float smg[];

__global__ __launch_bounds__(256, 2) void gemm_mma_kernel(GemmBatch7 bt)
{
    const GemmItem gi = bt.it[blockIdx.z];
    const int tid  = threadIdx.x;
    const int lane = tid & 31;
    const int warpId = tid >> 5;
    const int wm = warpId & 1;            // 2 warps along M
    const int wn = warpId >> 1;           // 4 warps along N
    const int rw = wm * 64, cw = wn * 32;
    const int gid = lane >> 2;            // groupID 0..7
    const int tig = lane & 3;             // thread-in-group 0..3

    const int bm = blockIdx.y, bn = blockIdx.x;
    const float* Ab = gi.A + (size_t)bm * BMG * C_;
    const float* Wb = gi.W + (size_t)bn * BNG * C_;

    const uint32_t smb = smem_u32(smg);
    const uint32_t* smU = reinterpret_cast<const uint32_t*>(smg);

    auto load_stage = [&](int s, int kt) {
        uint32_t sb = smb + s * (STF * 4);
        int k0 = kt * BKG;
#pragma unroll
        for (int i = 0; i < 4; i++) {
            int f = tid + i * 256;        // 0..1023
            int row = f >> 3;
            int ch  = f & 7;
            cp_async16(sb + row * (RS * 4) + ch * 16,
                       Ab + (size_t)row * C_ + k0 + ch * 4);
            cp_async16(sb + AST * 4 + row * (RS * 4) + ch * 16,
                       Wb + (size_t)row * C_ + k0 + ch * 4);
        }
        cp_commit();
    };

    float acc[16][4];
#pragma unroll
    for (int i = 0; i < 16; i++)
#pragma unroll
        for (int j = 0; j < 4; j++) acc[i][j] = 0.0f;

    uint32_t af[2][16], bf[2][8];

    load_stage(0, 0);
    load_stage(1, 1);

    for (int kt = 0; kt < NKT; kt++) {
        const int s = kt % 3;
        if (kt + 2 < NKT) cp_wait<1>(); else cp_wait<0>();
        __syncthreads();
        if (kt + 2 < NKT) load_stage((kt + 2) % 3, kt + 2);

        const int sbase = s * STF;
        const int aoff = sbase + (rw + gid) * RS + tig;
        const int boff = sbase + AST + (cw + gid) * RS + tig;

        auto ldA = [&](int buf, int kk) {
#pragma unroll
            for (int mt = 0; mt < 4; mt++) {
                int base = aoff + mt * (16 * RS) + kk * 8;
                af[buf][mt*4+0] = smU[base];
                af[buf][mt*4+1] = smU[base + 8 * RS];
                af[buf][mt*4+2] = smU[base + 4];
                af[buf][mt*4+3] = smU[base + 8 * RS + 4];
            }
        };
        auto ldB = [&](int buf, int kk) {
#pragma unroll
            for (int nt = 0; nt < 4; nt++) {
                int base = boff + nt * (8 * RS) + kk * 8;
                bf[buf][nt*2+0] = smU[base];
                bf[buf][nt*2+1] = smU[base + 4];
            }
        };

        ldA(0, 0); ldB(0, 0);
        int pb = 0;
#pragma unroll
        for (int kk = 0; kk < 4; kk++) {
            if (kk < 3) { ldA(pb ^ 1, kk + 1); ldB(pb ^ 1, kk + 1); }
#pragma unroll
            for (int mt = 0; mt < 4; mt++)
#pragma unroll
                for (int nt = 0; nt < 4; nt++)
                    MMA_TF32(acc[mt*4+nt], af[pb] + mt*4, bf[pb] + nt*2);
            pb ^= 1;
        }
    }

    // Epilogue
    const int act = gi.act;
    float* O = gi.O;
#pragma unroll
    for (int mt = 0; mt < 4; mt++) {
        int r0 = bm * BMG + rw + mt * 16 + gid;
#pragma unroll
        for (int nt = 0; nt < 4; nt++) {
            int col = bn * BNG + cw + nt * 8 + tig * 2;
            float v0 = acc[mt*4+nt][0], v1 = acc[mt*4+nt][1];
            float v2 = acc[mt*4+nt][2], v3 = acc[mt*4+nt][3];
            if (act == 1) {
                v0 = rtf(tanhf(v0)); v1 = rtf(tanhf(v1));
                v2 = rtf(tanhf(v2)); v3 = rtf(tanhf(v3));
            } else if (act == 2) {
                v0 = rtf(sigm(v0)); v1 = rtf(sigm(v1));
                v2 = rtf(sigm(v2)); v3 = rtf(sigm(v3));
            } else if (act == 3) {
                v0 = rtf(v0); v1 = rtf(v1); v2 = rtf(v2); v3 = rtf(v3);
            }
            *reinterpret_cast<float2*>(O + (size_t)r0 * C_ + col) = make_float2(v0, v1);
            *reinterpret_cast<float2*>(O + (size_t)(r0 + 8) * C_ + col) = make_float2(v2, v3);
        }
    }
}

// ---------------------------------------------------------------------------
// K5: stage-2 fused elementwise (w decay / k adjust / v blend), in place
// ---------------------------------------------------------------------------
__global__ __launch_bounds__(256) void ew2_kernel(
    float* __restrict__ w2, const float* __restrict__ a2, const float* __restrict__ v2,
    float* __restrict__ k, float* __restrict__ v, const float* __restrict__ v_first,
    const float* __restrict__ w0, const float* __restrict__ a0,
    const float* __restrict__ v0, const float* __restrict__ k_a)
{
    const int NC4 = C_ / 4;
    int e4 = blockIdx.x * 256 + threadIdx.x;
    if (e4 >= (int)(SLOT / 4)) return;
    int c4 = e4 % NC4;

    float4 w0v = reinterpret_cast<const float4*>(w0)[c4];
    float4 a0v = reinterpret_cast<const float4*>(a0)[c4];
    float4 v0v = reinterpret_cast<const float4*>(v0)[c4];
    float4 kav = reinterpret_cast<const float4*>(k_a)[c4];

    float4* W2v = reinterpret_cast<float4*>(w2);
    float4* Kv  = reinterpret_cast<float4*>(k);
    float4* Vv  = reinterpret_cast<float4*>(v);
    const float4* A2v = reinterpret_cast<const float4*>(a2);
    const float4* V2v = reinterpret_cast<const float4*>(v2);
    const float4* VFv = reinterpret_cast<const float4*>(v_first);

    float4 wr = W2v[e4];
    wr.x = expf(-0.606531f * sigm(w0v.x + wr.x));
    wr.y = expf(-0.606531f * sigm(w0v.y + wr.y));
    wr.z = expf(-0.606531f * sigm(w0v.z + wr.z));
    wr.w = expf(-0.606531f * sigm(w0v.w + wr.w));
    W2v[e4] = wr;

    float4 ar = A2v[e4];
    float ax = sigm(a0v.x + ar.x), ay = sigm(a0v.y + ar.y);
    float az = sigm(a0v.z + ar.z), aw = sigm(a0v.w + ar.w);
    float4 kv = Kv[e4];
    kv.x *= 1.0f + (ax - 1.0f) * kav.x;
    kv.y *= 1.0f + (ay - 1.0f) * kav.y;
    kv.z *= 1.0f + (az - 1.0f) * kav.z;
    kv.w *= 1.0f + (aw - 1.0f) * kav.w;
    Kv[e4] = kv;

    float4 vr = V2v[e4];
    float sx = sigm(v0v.x + vr.x), sy = sigm(v0v.y + vr.y);
    float sz = sigm(v0v.z + vr.z), sw = sigm(v0v.w + vr.w);
    float4 vv = Vv[e4];
    float4 vf = VFv[e4];
    vv.x += (vf.x - vv.x) * sx;
    vv.y += (vf.y - vv.y) * sy;
    vv.z += (vf.z - vv.z) * sz;
    vv.w += (vf.w - vv.w) * sw;
    Vv[e4] = vv;
}

// ---------------------------------------------------------------------------
// K6: WKV-7 scan (unchanged from R2)
// ---------------------------------------------------------------------------
__global__ __launch_bounds__(32) void wkv_kernel(
    const float* __restrict__ R, const float* __restrict__ Wd,
    const float* __restrict__ K, const float* __restrict__ V, float* __restrict__ Y)
{
    const int bh = blockIdx.x >> 4;
    const int rg = blockIdx.x & 15;
    const int b  = bh >> 4;
    const int h  = bh & 15;
    const int lane = threadIdx.x;
    const int i  = rg * 4 + (lane >> 3);
    const int jq = lane & 7;
    const size_t base = ((size_t)b * T_) * C_ + (size_t)h * NH;

    float S[8];
#pragma unroll
    for (int u = 0; u < 8; u++) S[u] = 0.0f;

    float4 rb[4][2], vb[4][2];
    float  wb[4], kb[4];

#pragma unroll
    for (int p = 0; p < 4; p++) {
        size_t q = base + (size_t)p * C_;
        const float4* r4 = reinterpret_cast<const float4*>(R + q + jq * 8);
        const float4* v4 = reinterpret_cast<const float4*>(V + q + jq * 8);
        rb[p][0] = r4[0]; rb[p][1] = r4[1];
        vb[p][0] = v4[0]; vb[p][1] = v4[1];
        wb[p] = Wd[q + i];
        kb[p] = K[q + i];
    }

    float yacc[4];

    for (int t0 = 0; t0 < T_; t0 += 4) {
#pragma unroll
        for (int s = 0; s < 4; s++) {
            const float wi = wb[s], ki = kb[s];
            float a0 = 0.f, a1 = 0.f;
            {
                float4 rv = rb[s][0], vv = vb[s][0];
                float t0v = S[0] * wi + ki * vv.x; S[0] = t0v; a0 += t0v * rv.x;
                float t1v = S[1] * wi + ki * vv.y; S[1] = t1v; a1 += t1v * rv.y;
                float t2v = S[2] * wi + ki * vv.z; S[2] = t2v; a0 += t2v * rv.z;
                float t3v = S[3] * wi + ki * vv.w; S[3] = t3v; a1 += t3v * rv.w;
            }
            {
                float4 rv = rb[s][1], vv = vb[s][1];
                float t0v = S[4] * wi + ki * vv.x; S[4] = t0v; a0 += t0v * rv.x;
                float t1v = S[5] * wi + ki * vv.y; S[5] = t1v; a1 += t1v * rv.y;
                float t2v = S[6] * wi + ki * vv.z; S[6] = t2v; a0 += t2v * rv.z;
                float t3v = S[7] * wi + ki * vv.w; S[7] = t3v; a1 += t3v * rv.w;
            }
            yacc[s] = a0 + a1;

            int tn = t0 + s + 4;
            if (tn < T_) {
                size_t q = base + (size_t)tn * C_;
                const float4* r4 = reinterpret_cast<const float4*>(R + q + jq * 8);
                const float4* v4 = reinterpret_cast<const float4*>(V + q + jq * 8);
                rb[s][0] = r4[0]; rb[s][1] = r4[1];
                vb[s][0] = v4[0]; vb[s][1] = v4[1];
                wb[s] = Wd[q + i];
                kb[s] = K[q + i];
            }
        }
#pragma unroll
        for (int s = 0; s < 4; s++) {
            float red = yacc[s];
            red += __shfl_xor_sync(0xffffffffu, red, 1);
            red += __shfl_xor_sync(0xffffffffu, red, 2);
            red += __shfl_xor_sync(0xffffffffu, red, 4);
            if (jq == 0) Y[base + (size_t)(t0 + s) * C_ + i] = red;
        }
    }
}

// ---------------------------------------------------------------------------
// K7: LayerNorm(C) + rkv residual + gate:  z = (LN(y) + rkv) * g   (tf32 out)
// ---------------------------------------------------------------------------
__global__ __launch_bounds__(256) void ln_gate_kernel(
    const float* __restrict__ Yb, const float* __restrict__ Rb, const float* __restrict__ Kb,
    const float* __restrict__ Vb, const float* __restrict__ Gb,
    const float* __restrict__ rk, const float* __restrict__ lng, const float* __restrict__ lnb,
    float* __restrict__ Zb)
{
    const int m = blockIdx.x;
    const size_t base = (size_t)m * C_;
    __shared__ float sprod[C_];
    __shared__ float hdot[H_];
    __shared__ float rs[8], rq[8], stats[2];

    const int tid = threadIdx.x;
    float yv[4];
    float lsum = 0.f, lsq = 0.f;
#pragma unroll
    for (int u = 0; u < 4; u++) {
        int c = tid + u * 256;
        float t = Yb[base + c];
        yv[u] = t; lsum += t; lsq += t * t;
        sprod[c] = Rb[base + c] * Kb[base + c] * rk[c];
    }
#pragma unroll
    for (int o = 16; o > 0; o >>= 1) {
        lsum += __shfl_xor_sync(0xffffffffu, lsum, o);
        lsq  += __shfl_xor_sync(0xffffffffu, lsq,  o);
    }
    if ((tid & 31) == 0) { rs[tid >> 5] = lsum; rq[tid >> 5] = lsq; }
    __syncthreads();
    if (tid == 0) {
        float s = 0.f, q = 0.f;
        for (int wq = 0; wq < 8; wq++) { s += rs[wq]; q += rq[wq]; }
        float mu = s / (float)C_;
        stats[0] = mu;
        stats[1] = rsqrtf(q / (float)C_ - mu * mu + 1e-5f);
    }
    if (tid < 16) {
        float d = 0.f;
        for (int n = 0; n < 64; n++) d += sprod[tid * 64 + n];
        hdot[tid] = d;
    }
    __syncthreads();
    const float mu = stats[0], rstd = stats[1];
#pragma unroll
    for (int u = 0; u < 4; u++) {
        int c = tid + u * 256;
        int hh = c >> 6;
        float z = ((yv[u] - mu) * rstd * lng[c] + lnb[c] + hdot[hh] * Vb[base + c]) * Gb[base + c];
        Zb[base + c] = rtf(z);
    }
}

// ---------------------------------------------------------------------------
// Launcher
// ---------------------------------------------------------------------------
extern "C" void kernel_launch(void* const* d_in, const int* in_sizes, int n_in,
                              void* d_out, int out_size)
{
    (void)in_sizes; (void)n_in; (void)out_size;
    const float* x       = (const float*)d_in[0];
    const float* v_first = (const float*)d_in[1];
    const float* Wr  = (const float*)d_in[2];
    const float* Wk  = (const float*)d_in[3];
    const float* Wv  = (const float*)d_in[4];
    const float* Wo  = (const float*)d_in[5];
    const float* Wg1 = (const float*)d_in[6];
    const float* Wg2 = (const float*)d_in[7];
    const float* W1  = (const float*)d_in[8];
    const float* W2  = (const float*)d_in[9];
    const float* A1  = (const float*)d_in[10];
    const float* A2  = (const float*)d_in[11];
    const float* V1  = (const float*)d_in[12];
    const float* V2  = (const float*)d_in[13];
    const float* tm_r = (const float*)d_in[14];
    const float* tm_w = (const float*)d_in[15];
    const float* tm_k = (const float*)d_in[16];
    const float* tm_v = (const float*)d_in[17];
    const float* tm_a = (const float*)d_in[18];
    const float* tm_g = (const float*)d_in[19];
    const float* w0  = (const float*)d_in[20];
    const float* a0  = (const float*)d_in[21];
    const float* v0  = (const float*)d_in[22];
    const float* k_a = (const float*)d_in[24];
    const float* r_k = (const float*)d_in[25];
    const float* ln_g = (const float*)d_in[26];
    const float* ln_b = (const float*)d_in[27];

    float* buf = nullptr;
    cudaGetSymbolAddress((void**)&buf, g_scratch);
    auto S  = [&](int s) { return buf + (size_t)s * SLOT; };
    float* wbase = buf + 19 * SLOT;
    auto WB = [&](int w) { return (const float*)(wbase + (size_t)w * WSLOT); };

    cudaFuncSetAttribute((const void*)gemm_mma_kernel,
                         cudaFuncAttributeMaxDynamicSharedMemorySize, GEMM_SMEM);

    const int EW_BLOCKS = MROWS * C_ / 4 / 256;   // 4096
    dim3 gg(C_ / BNG, MROWS / BMG);               // (8, 32)

    // K0: tf32-round the weights
    Ptr12 ws;
    ws.p[0] = Wr;  ws.p[1] = Wk;  ws.p[2] = Wv;  ws.p[3] = W1;
    ws.p[4] = A1;  ws.p[5] = V1;  ws.p[6] = Wg1; ws.p[7] = W2;
    ws.p[8] = A2;  ws.p[9] = V2;  ws.p[10] = Wg2; ws.p[11] = Wo;
    wcvt_kernel<<<dim3(1024, 12), 256>>>(ws, wbase);

    // K1: token-shift mixes -> slots 0..5, tf32-rounded
    mix_kernel<<<EW_BLOCKS, 256>>>(x, tm_r, tm_w, tm_k, tm_v, tm_a, tm_g, buf);

    // Stage-1 batched GEMMs (7)
    GemmBatch7 b1;
    b1.it[0] = { S(0), WB(0), S(6),  0 };   // r
    b1.it[1] = { S(2), WB(1), S(7),  0 };   // k
    b1.it[2] = { S(3), WB(2), S(8),  0 };   // v
    b1.it[3] = { S(1), WB(3), S(9),  1 };   // w1 = tanh(.)
    b1.it[4] = { S(4), WB(4), S(10), 3 };   // a1
    b1.it[5] = { S(3), WB(5), S(11), 3 };   // v1
    b1.it[6] = { S(5), WB(6), S(12), 2 };   // g1 = sigmoid(.)
    gemm_mma_kernel<<<dim3(gg.x, gg.y, 7), 256, GEMM_SMEM>>>(b1);

    // Stage-2 batched GEMMs (4)
    GemmBatch7 b2;
    b2.it[0] = { S(9),  WB(7),  S(13), 0 };
    b2.it[1] = { S(10), WB(8),  S(14), 0 };
    b2.it[2] = { S(11), WB(9),  S(15), 0 };
    b2.it[3] = { S(12), WB(10), S(16), 0 };
    gemm_mma_kernel<<<dim3(gg.x, gg.y, 4), 256, GEMM_SMEM>>>(b2);

    // K5: w decay, k adjust, v blend
    ew2_kernel<<<EW_BLOCKS, 256>>>(S(13), S(14), S(15), S(7), S(8), v_first,
                                   w0, a0, v0, k_a);

    // K6: WKV scan -> y
    wkv_kernel<<<512, 32>>>(S(6), S(13), S(7), S(8), S(17));

    // K7: LN + rkv + gate -> z, tf32-rounded
    ln_gate_kernel<<<MROWS, 256>>>(S(17), S(6), S(7), S(8), S(16),
                                   r_k, ln_g, ln_b, S(18));

    // Final GEMM: out = z @ Wo^T
    GemmBatch7 b3;
    b3.it[0] = { S(18), WB(11), (float*)d_out, 0 };
    gemm_mma_kernel<<<dim3(gg.x, gg.y, 1), 256, GEMM_SMEM>>>(b3);
}

// round 5
// speedup vs baseline: 1.9869x; 1.1540x over previous
#include <cuda_runtime.h>
#include <cuda_bf16.h>
#include <cstdint>
#include <cstddef>

// Problem dims
#define B_    2
#define T_    2048
#define C_    1024
#define H_    16
#define NH    64
#define MROWS 4096                       // B*T
constexpr size_t SLOT = (size_t)MROWS * C_;   // 4,194,304 elements per scratch slot
constexpr size_t WSLOT = (size_t)C_ * C_;     // 1,048,576 elements per weight

// Scratch slots:
// 0:xr 1:xw 2:xk 3:xv 4:xa 5:xg
// 6:r 7:k 8:v 9:w1(tanh'd) 10:a1 11:v1 12:g1(sigmoid'd)
// 13:w2raw(->w) 14:a2raw 15:v2raw 16:g 17:y 18:z
// then 12 tf32-rounded weight copies
__device__ float g_scratch[19ull * 4194304ull + 12ull * 1048576ull];

__device__ __forceinline__ float sigm(float x) { return 1.0f / (1.0f + expf(-x)); }
__device__ __forceinline__ float rtf(float x) {
    float r; asm("cvt.rna.tf32.f32 %0, %1;" : "=f"(r) : "f"(x)); return r;
}
__device__ __forceinline__ float4 rtf4(float4 v) {
    return make_float4(rtf(v.x), rtf(v.y), rtf(v.z), rtf(v.w));
}

__device__ __forceinline__ uint32_t smem_u32(const void* p) {
    uint32_t a;
    asm("{ .reg .u64 t; cvta.to.shared.u64 t, %1; cvt.u32.u64 %0, t; }" : "=r"(a) : "l"(p));
    return a;
}
__device__ __forceinline__ void cp_async16(uint32_t s, const void* g) {
    asm volatile("cp.async.ca.shared.global [%0], [%1], 16;\n" :: "r"(s), "l"(g));
}
__device__ __forceinline__ void cp_commit() { asm volatile("cp.async.commit_group;\n"); }
template <int Nn> __device__ __forceinline__ void cp_wait() {
    asm volatile("cp.async.wait_group %0;\n" :: "n"(Nn));
}

// ---------------------------------------------------------------------------
// K0: one-time tf32 rounding of the 12 weight matrices
// ---------------------------------------------------------------------------
struct Ptr12 { const float* p[12]; };

__global__ __launch_bounds__(256) void wcvt_kernel(Ptr12 ws, float* __restrict__ out)
{
    int w  = blockIdx.y;
    int e4 = blockIdx.x * 256 + threadIdx.x;   // 0..262143
    float4 v = reinterpret_cast<const float4*>(ws.p[w])[e4];
    reinterpret_cast<float4*>(out + (size_t)w * WSLOT)[e4] = rtf4(v);
}

// ---------------------------------------------------------------------------
// K1: token-shift mixing — 6 tf32-rounded outputs from one pass over x
// ---------------------------------------------------------------------------
__global__ __launch_bounds__(256) void mix_kernel(
    const float* __restrict__ X,
    const float* __restrict__ tmr, const float* __restrict__ tmw,
    const float* __restrict__ tmk, const float* __restrict__ tmv,
    const float* __restrict__ tma, const float* __restrict__ tmg,
    float* __restrict__ buf)
{
    const int NC4 = C_ / 4;
    int e4 = blockIdx.x * 256 + threadIdx.x;
    if (e4 >= MROWS * NC4) return;
    int m  = e4 / NC4;
    int c4 = e4 - m * NC4;
    int t  = m & (T_ - 1);

    const float4* X4 = reinterpret_cast<const float4*>(X);
    float4 xc = X4[e4];
    float4 xp = make_float4(0.f, 0.f, 0.f, 0.f);
    if (t != 0) xp = X4[e4 - NC4];
    float4 xx = make_float4(xp.x - xc.x, xp.y - xc.y, xp.z - xc.z, xp.w - xc.w);

    float4* out = reinterpret_cast<float4*>(buf);
    const float* tms[6] = {tmr, tmw, tmk, tmv, tma, tmg};
#pragma unroll
    for (int s = 0; s < 6; s++) {
        float4 tm = reinterpret_cast<const float4*>(tms[s])[c4];
        float4 o = make_float4(xc.x + xx.x * tm.x, xc.y + xx.y * tm.y,
                               xc.z + xx.z * tm.z, xc.w + xx.w * tm.w);
        out[(size_t)s * (SLOT / 4) + e4] = rtf4(o);
    }
}

// ---------------------------------------------------------------------------
// K2: hand-rolled TF32 mma GEMM   out[m,n] = sum_k A[m,k] * W[n,k]
// BM=BN=128, BK=32, 2-stage cp.async, 4 warps (2M x 2N), warp tile 64x64,
// register double-buffered fragments. 1.0 LDS per MMA. blockIdx.z = GEMM id.
// Epilogue act: 0 none, 1 tanh+round, 2 sigmoid+round, 3 round.
// ---------------------------------------------------------------------------
#define BMG 128
#define BNG 128
#define BKG 32
#define NKT (C_ / BKG)        // 32
#define RS  36                // padded row stride in floats (32 + 4)
#define AST (128 * RS)        // floats per matrix tile per stage (4608)
#define STF (2 * AST)         // floats per stage (9216)
constexpr int GEMM_SMEM = 2 * STF * 4;   // 73728 bytes

struct GemmItem { const float* A; const float* W; float* O; int act; };
struct GemmBatch7 { GemmItem it[7]; };

#define MMA_TF32(d, a, b) \
    asm volatile( \
        "mma.sync.aligned.m16n8k8.row.col.f32.tf32.tf32.f32 " \
        "{%0,%1,%2,%3}, {%4,%5,%6,%7}, {%8,%9}, {%0,%1,%2,%3};" \
        : "+f"((d)[0]), "+f"((d)[1]), "+f"((d)[2]), "+f"((d)[3]) \
        : "r"((a)[0]), "r"((a)[1]), "r"((a)[2]), "r"((a)[3]), \
          "r"((b)[0]), "r"((b)[1]))

extern __shared__ float smg[];

__global__ __launch_bounds__(128, 2) void gemm_mma_kernel(GemmBatch7 bt)
{
    const GemmItem gi = bt.it[blockIdx.z];
    const int tid  = threadIdx.x;
    const int lane = tid & 31;
    const int warpId = tid >> 5;
    const int wm = warpId & 1;            // 2 warps along M
    const int wn = warpId >> 1;           // 2 warps along N
    const int rw = wm * 64, cw = wn * 64;
    const int gid = lane >> 2;            // groupID 0..7
    const int tig = lane & 3;             // thread-in-group 0..3

    const int bm = blockIdx.y, bn = blockIdx.x;
    const float* Ab = gi.A + (size_t)bm * BMG * C_;
    const float* Wb = gi.W + (size_t)bn * BNG * C_;

    const uint32_t smb = smem_u32(smg);
    const uint32_t* smU = reinterpret_cast<const uint32_t*>(smg);

    auto load_stage = [&](int s, int kt) {
        uint32_t sb = smb + s * (STF * 4);
        int k0 = kt * BKG;
#pragma unroll
        for (int i = 0; i < 8; i++) {
            int f = tid + i * 128;        // 0..1023
            int row = f >> 3;
            int ch  = f & 7;
            cp_async16(sb + row * (RS * 4) + ch * 16,
                       Ab + (size_t)row * C_ + k0 + ch * 4);
            cp_async16(sb + AST * 4 + row * (RS * 4) + ch * 16,
                       Wb + (size_t)row * C_ + k0 + ch * 4);
        }
        cp_commit();
    };

    float acc[32][4];
#pragma unroll
    for (int i = 0; i < 32; i++)
#pragma unroll
        for (int j = 0; j < 4; j++) acc[i][j] = 0.0f;

    uint32_t af[2][16], bf[2][16];

    load_stage(0, 0);
    load_stage(1, 1);

    for (int kt = 0; kt < NKT; kt++) {
        const int s = kt & 1;
        if (kt + 1 < NKT) cp_wait<1>(); else cp_wait<0>();
        __syncthreads();

        const int sbase = s * STF;
        const int aoff = sbase + (rw + gid) * RS + tig;
        const int boff = sbase + AST + (cw + gid) * RS + tig;

        auto ldA = [&](int buf, int kk) {
#pragma unroll
            for (int mt = 0; mt < 4; mt++) {
                int base = aoff + mt * (16 * RS) + kk * 8;
                af[buf][mt*4+0] = smU[base];
                af[buf][mt*4+1] = smU[base + 8 * RS];
                af[buf][mt*4+2] = smU[base + 4];
                af[buf][mt*4+3] = smU[base + 8 * RS + 4];
            }
        };
        auto ldB = [&](int buf, int kk) {
#pragma unroll
            for (int nt = 0; nt < 8; nt++) {
                int base = boff + nt * (8 * RS) + kk * 8;
                bf[buf][nt*2+0] = smU[base];
                bf[buf][nt*2+1] = smU[base + 4];
            }
        };

        ldA(0, 0); ldB(0, 0);
        int pb = 0;
#pragma unroll
        for (int kk = 0; kk < 4; kk++) {
            if (kk < 3) { ldA(pb ^ 1, kk + 1); ldB(pb ^ 1, kk + 1); }
#pragma unroll
            for (int mt = 0; mt < 4; mt++)
#pragma unroll
                for (int nt = 0; nt < 8; nt++)
                    MMA_TF32(acc[mt*8+nt], af[pb] + mt*4, bf[pb] + nt*2);
            pb ^= 1;
        }

        __syncthreads();                 // all warps done reading stage s
        if (kt + 2 < NKT) load_stage(s, kt + 2);
    }

    // Epilogue
    const int act = gi.act;
    float* O = gi.O;
#pragma unroll
    for (int mt = 0; mt < 4; mt++) {
        int r0 = bm * BMG + rw + mt * 16 + gid;
#pragma unroll
        for (int nt = 0; nt < 8; nt++) {
            int col = bn * BNG + cw + nt * 8 + tig * 2;
            float v0 = acc[mt*8+nt][0], v1 = acc[mt*8+nt][1];
            float v2 = acc[mt*8+nt][2], v3 = acc[mt*8+nt][3];
            if (act == 1) {
                v0 = rtf(tanhf(v0)); v1 = rtf(tanhf(v1));
                v2 = rtf(tanhf(v2)); v3 = rtf(tanhf(v3));
            } else if (act == 2) {
                v0 = rtf(sigm(v0)); v1 = rtf(sigm(v1));
                v2 = rtf(sigm(v2)); v3 = rtf(sigm(v3));
            } else if (act == 3) {
                v0 = rtf(v0); v1 = rtf(v1); v2 = rtf(v2); v3 = rtf(v3);
            }
            *reinterpret_cast<float2*>(O + (size_t)r0 * C_ + col) = make_float2(v0, v1);
            *reinterpret_cast<float2*>(O + (size_t)(r0 + 8) * C_ + col) = make_float2(v2, v3);
        }
    }
}

// ---------------------------------------------------------------------------
// K5: stage-2 fused elementwise (w decay / k adjust / v blend), in place
// ---------------------------------------------------------------------------
__global__ __launch_bounds__(256) void ew2_kernel(
    float* __restrict__ w2, const float* __restrict__ a2, const float* __restrict__ v2,
    float* __restrict__ k, float* __restrict__ v, const float* __restrict__ v_first,
    const float* __restrict__ w0, const float* __restrict__ a0,
    const float* __restrict__ v0, const float* __restrict__ k_a)
{
    const int NC4 = C_ / 4;
    int e4 = blockIdx.x * 256 + threadIdx.x;
    if (e4 >= (int)(SLOT / 4)) return;
    int c4 = e4 % NC4;

    float4 w0v = reinterpret_cast<const float4*>(w0)[c4];
    float4 a0v = reinterpret_cast<const float4*>(a0)[c4];
    float4 v0v = reinterpret_cast<const float4*>(v0)[c4];
    float4 kav = reinterpret_cast<const float4*>(k_a)[c4];

    float4* W2v = reinterpret_cast<float4*>(w2);
    float4* Kv  = reinterpret_cast<float4*>(k);
    float4* Vv  = reinterpret_cast<float4*>(v);
    const float4* A2v = reinterpret_cast<const float4*>(a2);
    const float4* V2v = reinterpret_cast<const float4*>(v2);
    const float4* VFv = reinterpret_cast<const float4*>(v_first);

    float4 wr = W2v[e4];
    wr.x = expf(-0.606531f * sigm(w0v.x + wr.x));
    wr.y = expf(-0.606531f * sigm(w0v.y + wr.y));
    wr.z = expf(-0.606531f * sigm(w0v.z + wr.z));
    wr.w = expf(-0.606531f * sigm(w0v.w + wr.w));
    W2v[e4] = wr;

    float4 ar = A2v[e4];
    float ax = sigm(a0v.x + ar.x), ay = sigm(a0v.y + ar.y);
    float az = sigm(a0v.z + ar.z), aw = sigm(a0v.w + ar.w);
    float4 kv = Kv[e4];
    kv.x *= 1.0f + (ax - 1.0f) * kav.x;
    kv.y *= 1.0f + (ay - 1.0f) * kav.y;
    kv.z *= 1.0f + (az - 1.0f) * kav.z;
    kv.w *= 1.0f + (aw - 1.0f) * kav.w;
    Kv[e4] = kv;

    float4 vr = V2v[e4];
    float sx = sigm(v0v.x + vr.x), sy = sigm(v0v.y + vr.y);
    float sz = sigm(v0v.z + vr.z), sw = sigm(v0v.w + vr.w);
    float4 vv = Vv[e4];
    float4 vf = VFv[e4];
    vv.x += (vf.x - vv.x) * sx;
    vv.y += (vf.y - vv.y) * sy;
    vv.z += (vf.z - vv.z) * sz;
    vv.w += (vf.w - vv.w) * sw;
    Vv[e4] = vv;
}

// ---------------------------------------------------------------------------
// K6: WKV-7 scan (unchanged)
// ---------------------------------------------------------------------------
__global__ __launch_bounds__(32) void wkv_kernel(
    const float* __restrict__ R, const float* __restrict__ Wd,
    const float* __restrict__ K, const float* __restrict__ V, float* __restrict__ Y)
{
    const int bh = blockIdx.x >> 4;
    const int rg = blockIdx.x & 15;
    const int b  = bh >> 4;
    const int h  = bh & 15;
    const int lane = threadIdx.x;
    const int i  = rg * 4 + (lane >> 3);
    const int jq = lane & 7;
    const size_t base = ((size_t)b * T_) * C_ + (size_t)h * NH;

    float S[8];
#pragma unroll
    for (int u = 0; u < 8; u++) S[u] = 0.0f;

    float4 rb[4][2], vb[4][2];
    float  wb[4], kb[4];

#pragma unroll
    for (int p = 0; p < 4; p++) {
        size_t q = base + (size_t)p * C_;
        const float4* r4 = reinterpret_cast<const float4*>(R + q + jq * 8);
        const float4* v4 = reinterpret_cast<const float4*>(V + q + jq * 8);
        rb[p][0] = r4[0]; rb[p][1] = r4[1];
        vb[p][0] = v4[0]; vb[p][1] = v4[1];
        wb[p] = Wd[q + i];
        kb[p] = K[q + i];
    }

    float yacc[4];

    for (int t0 = 0; t0 < T_; t0 += 4) {
#pragma unroll
        for (int s = 0; s < 4; s++) {
            const float wi = wb[s], ki = kb[s];
            float a0 = 0.f, a1 = 0.f;
            {
                float4 rv = rb[s][0], vv = vb[s][0];
                float t0v = S[0] * wi + ki * vv.x; S[0] = t0v; a0 += t0v * rv.x;
                float t1v = S[1] * wi + ki * vv.y; S[1] = t1v; a1 += t1v * rv.y;
                float t2v = S[2] * wi + ki * vv.z; S[2] = t2v; a0 += t2v * rv.z;
                float t3v = S[3] * wi + ki * vv.w; S[3] = t3v; a1 += t3v * rv.w;
            }
            {
                float4 rv = rb[s][1], vv = vb[s][1];
                float t0v = S[4] * wi + ki * vv.x; S[4] = t0v; a0 += t0v * rv.x;
                float t1v = S[5] * wi + ki * vv.y; S[5] = t1v; a1 += t1v * rv.y;
                float t2v = S[6] * wi + ki * vv.z; S[6] = t2v; a0 += t2v * rv.z;
                float t3v = S[7] * wi + ki * vv.w; S[7] = t3v; a1 += t3v * rv.w;
            }
            yacc[s] = a0 + a1;

            int tn = t0 + s + 4;
            if (tn < T_) {
                size_t q = base + (size_t)tn * C_;
                const float4* r4 = reinterpret_cast<const float4*>(R + q + jq * 8);
                const float4* v4 = reinterpret_cast<const float4*>(V + q + jq * 8);
                rb[s][0] = r4[0]; rb[s][1] = r4[1];
                vb[s][0] = v4[0]; vb[s][1] = v4[1];
                wb[s] = Wd[q + i];
                kb[s] = K[q + i];
            }
        }
#pragma unroll
        for (int s = 0; s < 4; s++) {
            float red = yacc[s];
            red += __shfl_xor_sync(0xffffffffu, red, 1);
            red += __shfl_xor_sync(0xffffffffu, red, 2);
            red += __shfl_xor_sync(0xffffffffu, red, 4);
            if (jq == 0) Y[base + (size_t)(t0 + s) * C_ + i] = red;
        }
    }
}

// ---------------------------------------------------------------------------
// K7: LayerNorm(C) + rkv residual + gate:  z = (LN(y) + rkv) * g   (tf32 out)
// ---------------------------------------------------------------------------
__global__ __launch_bounds__(256) void ln_gate_kernel(
    const float* __restrict__ Yb, const float* __restrict__ Rb, const float* __restrict__ Kb,
    const float* __restrict__ Vb, const float* __restrict__ Gb,
    const float* __restrict__ rk, const float* __restrict__ lng, const float* __restrict__ lnb,
    float* __restrict__ Zb)
{
    const int m = blockIdx.x;
    const size_t base = (size_t)m * C_;
    __shared__ float sprod[C_];
    __shared__ float hdot[H_];
    __shared__ float rs[8], rq[8], stats[2];

    const int tid = threadIdx.x;
    float yv[4];
    float lsum = 0.f, lsq = 0.f;
#pragma unroll
    for (int u = 0; u < 4; u++) {
        int c = tid + u * 256;
        float t = Yb[base + c];
        yv[u] = t; lsum += t; lsq += t * t;
        sprod[c] = Rb[base + c] * Kb[base + c] * rk[c];
    }
#pragma unroll
    for (int o = 16; o > 0; o >>= 1) {
        lsum += __shfl_xor_sync(0xffffffffu, lsum, o);
        lsq  += __shfl_xor_sync(0xffffffffu, lsq,  o);
    }
    if ((tid & 31) == 0) { rs[tid >> 5] = lsum; rq[tid >> 5] = lsq; }
    __syncthreads();
    if (tid == 0) {
        float s = 0.f, q = 0.f;
        for (int wq = 0; wq < 8; wq++) { s += rs[wq]; q += rq[wq]; }
        float mu = s / (float)C_;
        stats[0] = mu;
        stats[1] = rsqrtf(q / (float)C_ - mu * mu + 1e-5f);
    }
    if (tid < 16) {
        float d = 0.f;
        for (int n = 0; n < 64; n++) d += sprod[tid * 64 + n];
        hdot[tid] = d;
    }
    __syncthreads();
    const float mu = stats[0], rstd = stats[1];
#pragma unroll
    for (int u = 0; u < 4; u++) {
        int c = tid + u * 256;
        int hh = c >> 6;
        float z = ((yv[u] - mu) * rstd * lng[c] + lnb[c] + hdot[hh] * Vb[base + c]) * Gb[base + c];
        Zb[base + c] = rtf(z);
    }
}

// ---------------------------------------------------------------------------
// Launcher
// ---------------------------------------------------------------------------
extern "C" void kernel_launch(void* const* d_in, const int* in_sizes, int n_in,
                              void* d_out, int out_size)
{
    (void)in_sizes; (void)n_in; (void)out_size;
    const float* x       = (const float*)d_in[0];
    const float* v_first = (const float*)d_in[1];
    const float* Wr  = (const float*)d_in[2];
    const float* Wk  = (const float*)d_in[3];
    const float* Wv  = (const float*)d_in[4];
    const float* Wo  = (const float*)d_in[5];
    const float* Wg1 = (const float*)d_in[6];
    const float* Wg2 = (const float*)d_in[7];
    const float* W1  = (const float*)d_in[8];
    const float* W2  = (const float*)d_in[9];
    const float* A1  = (const float*)d_in[10];
    const float* A2  = (const float*)d_in[11];
    const float* V1  = (const float*)d_in[12];
    const float* V2  = (const float*)d_in[13];
    const float* tm_r = (const float*)d_in[14];
    const float* tm_w = (const float*)d_in[15];
    const float* tm_k = (const float*)d_in[16];
    const float* tm_v = (const float*)d_in[17];
    const float* tm_a = (const float*)d_in[18];
    const float* tm_g = (const float*)d_in[19];
    const float* w0  = (const float*)d_in[20];
    const float* a0  = (const float*)d_in[21];
    const float* v0  = (const float*)d_in[22];
    const float* k_a = (const float*)d_in[24];
    const float* r_k = (const float*)d_in[25];
    const float* ln_g = (const float*)d_in[26];
    const float* ln_b = (const float*)d_in[27];

    float* buf = nullptr;
    cudaGetSymbolAddress((void**)&buf, g_scratch);
    auto S  = [&](int s) { return buf + (size_t)s * SLOT; };
    float* wbase = buf + 19 * SLOT;
    auto WB = [&](int w) { return (const float*)(wbase + (size_t)w * WSLOT); };

    cudaFuncSetAttribute((const void*)gemm_mma_kernel,
                         cudaFuncAttributeMaxDynamicSharedMemorySize, GEMM_SMEM);

    const int EW_BLOCKS = MROWS * C_ / 4 / 256;   // 4096
    dim3 gg(C_ / BNG, MROWS / BMG);               // (8, 32)

    // K0: tf32-round the weights
    Ptr12 ws;
    ws.p[0] = Wr;  ws.p[1] = Wk;  ws.p[2] = Wv;  ws.p[3] = W1;
    ws.p[4] = A1;  ws.p[5] = V1;  ws.p[6] = Wg1; ws.p[7] = W2;
    ws.p[8] = A2;  ws.p[9] = V2;  ws.p[10] = Wg2; ws.p[11] = Wo;
    wcvt_kernel<<<dim3(1024, 12), 256>>>(ws, wbase);

    // K1: token-shift mixes -> slots 0..5, tf32-rounded
    mix_kernel<<<EW_BLOCKS, 256>>>(x, tm_r, tm_w, tm_k, tm_v, tm_a, tm_g, buf);

    // Stage-1 batched GEMMs (7)
    GemmBatch7 b1;
    b1.it[0] = { S(0), WB(0), S(6),  0 };   // r
    b1.it[1] = { S(2), WB(1), S(7),  0 };   // k
    b1.it[2] = { S(3), WB(2), S(8),  0 };   // v
    b1.it[3] = { S(1), WB(3), S(9),  1 };   // w1 = tanh(.)
    b1.it[4] = { S(4), WB(4), S(10), 3 };   // a1
    b1.it[5] = { S(3), WB(5), S(11), 3 };   // v1
    b1.it[6] = { S(5), WB(6), S(12), 2 };   // g1 = sigmoid(.)
    gemm_mma_kernel<<<dim3(gg.x, gg.y, 7), 128, GEMM_SMEM>>>(b1);

    // Stage-2 batched GEMMs (4)
    GemmBatch7 b2;
    b2.it[0] = { S(9),  WB(7),  S(13), 0 };
    b2.it[1] = { S(10), WB(8),  S(14), 0 };
    b2.it[2] = { S(11), WB(9),  S(15), 0 };
    b2.it[3] = { S(12), WB(10), S(16), 0 };
    gemm_mma_kernel<<<dim3(gg.x, gg.y, 4), 128, GEMM_SMEM>>>(b2);

    // K5: w decay, k adjust, v blend
    ew2_kernel<<<EW_BLOCKS, 256>>>(S(13), S(14), S(15), S(7), S(8), v_first,
                                   w0, a0, v0, k_a);

    // K6: WKV scan -> y
    wkv_kernel<<<512, 32>>>(S(6), S(13), S(7), S(8), S(17));

    // K7: LN + rkv + gate -> z, tf32-rounded
    ln_gate_kernel<<<MROWS, 256>>>(S(17), S(6), S(7), S(8), S(16),
                                   r_k, ln_g, ln_b, S(18));

    // Final GEMM: out = z @ Wo^T
    GemmBatch7 b3;
    b3.it[0] = { S(18), WB(11), (float*)d_out, 0 };
    gemm_mma_kernel<<<dim3(gg.x, gg.y, 1), 128, GEMM_SMEM>>>(b3);
}

// round 6
// speedup vs baseline: 2.0950x; 1.0544x over previous
#include <cuda_runtime.h>
#include <cuda_bf16.h>
#include <cstdint>
#include <cstddef>

// Problem dims
#define B_    2
#define T_    2048
#define C_    1024
#define H_    16
#define NH    64
#define MROWS 4096                       // B*T
constexpr size_t SLOT = (size_t)MROWS * C_;   // 4,194,304 elements per scratch slot
constexpr size_t WSLOT = (size_t)C_ * C_;     // 1,048,576 elements per weight

// Scratch slots:
// 0:xr 1:xw 2:xk 3:xv 4:xa 5:xg
// 6:r 7:k 8:v 9:w1(tanh'd) 10:a1 11:v1 12:g1(sigmoid'd)
// 13:w2raw(->w) 14:a2raw 15:v2raw 16:g 17:y 18:z
// then 12 tf32-rounded weight copies
__device__ float g_scratch[19ull * 4194304ull + 12ull * 1048576ull];

__device__ __forceinline__ float sigm(float x) { return 1.0f / (1.0f + expf(-x)); }
__device__ __forceinline__ float rtf(float x) {
    float r; asm("cvt.rna.tf32.f32 %0, %1;" : "=f"(r) : "f"(x)); return r;
}
__device__ __forceinline__ float4 rtf4(float4 v) {
    return make_float4(rtf(v.x), rtf(v.y), rtf(v.z), rtf(v.w));
}

__device__ __forceinline__ uint32_t smem_u32(const void* p) {
    uint32_t a;
    asm("{ .reg .u64 t; cvta.to.shared.u64 t, %1; cvt.u32.u64 %0, t; }" : "=r"(a) : "l"(p));
    return a;
}
__device__ __forceinline__ void cp_async16(uint32_t s, const void* g) {
    asm volatile("cp.async.ca.shared.global [%0], [%1], 16;\n" :: "r"(s), "l"(g));
}
__device__ __forceinline__ void cp_commit() { asm volatile("cp.async.commit_group;\n"); }
template <int Nn> __device__ __forceinline__ void cp_wait() {
    asm volatile("cp.async.wait_group %0;\n" :: "n"(Nn));
}

// ---------------------------------------------------------------------------
// K0: one-time tf32 rounding of the 12 weight matrices
// ---------------------------------------------------------------------------
struct Ptr12 { const float* p[12]; };

__global__ __launch_bounds__(256) void wcvt_kernel(Ptr12 ws, float* __restrict__ out)
{
    int w  = blockIdx.y;
    int e4 = blockIdx.x * 256 + threadIdx.x;   // 0..262143
    float4 v = reinterpret_cast<const float4*>(ws.p[w])[e4];
    reinterpret_cast<float4*>(out + (size_t)w * WSLOT)[e4] = rtf4(v);
}

// ---------------------------------------------------------------------------
// K1: token-shift mixing — 6 tf32-rounded outputs from one pass over x
// ---------------------------------------------------------------------------
__global__ __launch_bounds__(256) void mix_kernel(
    const float* __restrict__ X,
    const float* __restrict__ tmr, const float* __restrict__ tmw,
    const float* __restrict__ tmk, const float* __restrict__ tmv,
    const float* __restrict__ tma, const float* __restrict__ tmg,
    float* __restrict__ buf)
{
    const int NC4 = C_ / 4;
    int e4 = blockIdx.x * 256 + threadIdx.x;
    if (e4 >= MROWS * NC4) return;
    int m  = e4 / NC4;
    int c4 = e4 - m * NC4;
    int t  = m & (T_ - 1);

    const float4* X4 = reinterpret_cast<const float4*>(X);
    float4 xc = X4[e4];
    float4 xp = make_float4(0.f, 0.f, 0.f, 0.f);
    if (t != 0) xp = X4[e4 - NC4];
    float4 xx = make_float4(xp.x - xc.x, xp.y - xc.y, xp.z - xc.z, xp.w - xc.w);

    float4* out = reinterpret_cast<float4*>(buf);
    const float* tms[6] = {tmr, tmw, tmk, tmv, tma, tmg};
#pragma unroll
    for (int s = 0; s < 6; s++) {
        float4 tm = reinterpret_cast<const float4*>(tms[s])[c4];
        float4 o = make_float4(xc.x + xx.x * tm.x, xc.y + xx.y * tm.y,
                               xc.z + xx.z * tm.z, xc.w + xx.w * tm.w);
        out[(size_t)s * (SLOT / 4) + e4] = rtf4(o);
    }
}

// ---------------------------------------------------------------------------
// K2: hand-rolled TF32 mma GEMM   out[m,n] = sum_k A[m,k] * W[n,k]
// BM=BN=128, BK=16, 4-stage cp.async, single sync per k-tile, 4 warps
// (2M x 2N), warp tile 64x64, register double-buffered fragments.
// Epilogue act: 0 none, 1 tanh+round, 2 sigmoid+round, 3 round.
// ---------------------------------------------------------------------------
#define BMG 128
#define BNG 128
#define BKG 16
#define NKT (C_ / BKG)        // 64
#define RS  20                // padded row stride in floats (16 + 4)
#define AST (128 * RS)        // floats per matrix tile per stage (2560)
#define STF (2 * AST)         // floats per stage (5120)
#define NST 4
constexpr int GEMM_SMEM = NST * STF * 4;   // 81920 bytes

struct GemmItem { const float* A; const float* W; float* O; int act; };
struct GemmBatch7 { GemmItem it[7]; };

#define MMA_TF32(d, a, b) \
    asm volatile( \
        "mma.sync.aligned.m16n8k8.row.col.f32.tf32.tf32.f32 " \
        "{%0,%1,%2,%3}, {%4,%5,%6,%7}, {%8,%9}, {%0,%1,%2,%3};" \
        : "+f"((d)[0]), "+f"((d)[1]), "+f"((d)[2]), "+f"((d)[3]) \
        : "r"((a)[0]), "r"((a)[1]), "r"((a)[2]), "r"((a)[3]), \
          "r"((b)[0]), "r"((b)[1]))

extern __shared__ float smg[];

__global__ __launch_bounds__(128, 2) void gemm_mma_kernel(GemmBatch7 bt)
{
    const GemmItem gi = bt.it[blockIdx.z];
    const int tid  = threadIdx.x;
    const int lane = tid & 31;
    const int warpId = tid >> 5;
    const int wm = warpId & 1;            // 2 warps along M
    const int wn = warpId >> 1;           // 2 warps along N
    const int rw = wm * 64, cw = wn * 64;
    const int gid = lane >> 2;            // groupID 0..7
    const int tig = lane & 3;             // thread-in-group 0..3

    const int bm = blockIdx.y, bn = blockIdx.x;
    const float* Ab = gi.A + (size_t)bm * BMG * C_;
    const float* Wb = gi.W + (size_t)bn * BNG * C_;

    const uint32_t smb = smem_u32(smg);
    const uint32_t* smU = reinterpret_cast<const uint32_t*>(smg);

    auto load_stage = [&](int st, int kt) {
        uint32_t sb = smb + st * (STF * 4);
        int k0 = kt * BKG;
#pragma unroll
        for (int i = 0; i < 4; i++) {
            int f = tid + i * 128;        // 0..511
            int row = f >> 2;
            int ch  = f & 3;
            cp_async16(sb + row * (RS * 4) + ch * 16,
                       Ab + (size_t)row * C_ + k0 + ch * 4);
            cp_async16(sb + AST * 4 + row * (RS * 4) + ch * 16,
                       Wb + (size_t)row * C_ + k0 + ch * 4);
        }
    };

    float acc[32][4];
#pragma unroll
    for (int i = 0; i < 32; i++)
#pragma unroll
        for (int j = 0; j < 4; j++) acc[i][j] = 0.0f;

    uint32_t af[2][16], bf[2][16];

    load_stage(0, 0); cp_commit();
    load_stage(1, 1); cp_commit();
    load_stage(2, 2); cp_commit();

    for (int kt = 0; kt < NKT; kt++) {
        cp_wait<2>();
        __syncthreads();
        if (kt + 3 < NKT) load_stage((kt + 3) & 3, kt + 3);
        cp_commit();

        const int sbase = (kt & 3) * STF;
        const int aoff = sbase + (rw + gid) * RS + tig;
        const int boff = sbase + AST + (cw + gid) * RS + tig;

        auto ldA = [&](int buf, int kk) {
#pragma unroll
            for (int mt = 0; mt < 4; mt++) {
                int base = aoff + mt * (16 * RS) + kk * 8;
                af[buf][mt*4+0] = smU[base];
                af[buf][mt*4+1] = smU[base + 8 * RS];
                af[buf][mt*4+2] = smU[base + 4];
                af[buf][mt*4+3] = smU[base + 8 * RS + 4];
            }
        };
        auto ldB = [&](int buf, int kk) {
#pragma unroll
            for (int nt = 0; nt < 8; nt++) {
                int base = boff + nt * (8 * RS) + kk * 8;
                bf[buf][nt*2+0] = smU[base];
                bf[buf][nt*2+1] = smU[base + 4];
            }
        };

        ldA(0, 0); ldB(0, 0);
        ldA(1, 1); ldB(1, 1);
#pragma unroll
        for (int mt = 0; mt < 4; mt++)
#pragma unroll
            for (int nt = 0; nt < 8; nt++)
                MMA_TF32(acc[mt*8+nt], af[0] + mt*4, bf[0] + nt*2);
#pragma unroll
        for (int mt = 0; mt < 4; mt++)
#pragma unroll
            for (int nt = 0; nt < 8; nt++)
                MMA_TF32(acc[mt*8+nt], af[1] + mt*4, bf[1] + nt*2);
    }

    // Epilogue
    const int act = gi.act;
    float* O = gi.O;
#pragma unroll
    for (int mt = 0; mt < 4; mt++) {
        int r0 = bm * BMG + rw + mt * 16 + gid;
#pragma unroll
        for (int nt = 0; nt < 8; nt++) {
            int col = bn * BNG + cw + nt * 8 + tig * 2;
            float v0 = acc[mt*8+nt][0], v1 = acc[mt*8+nt][1];
            float v2 = acc[mt*8+nt][2], v3 = acc[mt*8+nt][3];
            if (act == 1) {
                v0 = rtf(tanhf(v0)); v1 = rtf(tanhf(v1));
                v2 = rtf(tanhf(v2)); v3 = rtf(tanhf(v3));
            } else if (act == 2) {
                v0 = rtf(sigm(v0)); v1 = rtf(sigm(v1));
                v2 = rtf(sigm(v2)); v3 = rtf(sigm(v3));
            } else if (act == 3) {
                v0 = rtf(v0); v1 = rtf(v1); v2 = rtf(v2); v3 = rtf(v3);
            }
            *reinterpret_cast<float2*>(O + (size_t)r0 * C_ + col) = make_float2(v0, v1);
            *reinterpret_cast<float2*>(O + (size_t)(r0 + 8) * C_ + col) = make_float2(v2, v3);
        }
    }
}

// ---------------------------------------------------------------------------
// K5: stage-2 fused elementwise (w decay / k adjust / v blend), in place
// ---------------------------------------------------------------------------
__global__ __launch_bounds__(256) void ew2_kernel(
    float* __restrict__ w2, const float* __restrict__ a2, const float* __restrict__ v2,
    float* __restrict__ k, float* __restrict__ v, const float* __restrict__ v_first,
    const float* __restrict__ w0, const float* __restrict__ a0,
    const float* __restrict__ v0, const float* __restrict__ k_a)
{
    const int NC4 = C_ / 4;
    int e4 = blockIdx.x * 256 + threadIdx.x;
    if (e4 >= (int)(SLOT / 4)) return;
    int c4 = e4 % NC4;

    float4 w0v = reinterpret_cast<const float4*>(w0)[c4];
    float4 a0v = reinterpret_cast<const float4*>(a0)[c4];
    float4 v0v = reinterpret_cast<const float4*>(v0)[c4];
    float4 kav = reinterpret_cast<const float4*>(k_a)[c4];

    float4* W2v = reinterpret_cast<float4*>(w2);
    float4* Kv  = reinterpret_cast<float4*>(k);
    float4* Vv  = reinterpret_cast<float4*>(v);
    const float4* A2v = reinterpret_cast<const float4*>(a2);
    const float4* V2v = reinterpret_cast<const float4*>(v2);
    const float4* VFv = reinterpret_cast<const float4*>(v_first);

    float4 wr = W2v[e4];
    wr.x = expf(-0.606531f * sigm(w0v.x + wr.x));
    wr.y = expf(-0.606531f * sigm(w0v.y + wr.y));
    wr.z = expf(-0.606531f * sigm(w0v.z + wr.z));
    wr.w = expf(-0.606531f * sigm(w0v.w + wr.w));
    W2v[e4] = wr;

    float4 ar = A2v[e4];
    float ax = sigm(a0v.x + ar.x), ay = sigm(a0v.y + ar.y);
    float az = sigm(a0v.z + ar.z), aw = sigm(a0v.w + ar.w);
    float4 kv = Kv[e4];
    kv.x *= 1.0f + (ax - 1.0f) * kav.x;
    kv.y *= 1.0f + (ay - 1.0f) * kav.y;
    kv.z *= 1.0f + (az - 1.0f) * kav.z;
    kv.w *= 1.0f + (aw - 1.0f) * kav.w;
    Kv[e4] = kv;

    float4 vr = V2v[e4];
    float sx = sigm(v0v.x + vr.x), sy = sigm(v0v.y + vr.y);
    float sz = sigm(v0v.z + vr.z), sw = sigm(v0v.w + vr.w);
    float4 vv = Vv[e4];
    float4 vf = VFv[e4];
    vv.x += (vf.x - vv.x) * sx;
    vv.y += (vf.y - vv.y) * sy;
    vv.z += (vf.z - vv.z) * sz;
    vv.w += (vf.w - vv.w) * sw;
    Vv[e4] = vv;
}

// ---------------------------------------------------------------------------
// K6: WKV-7 scan — smem-chunked.
// 128 blocks x 128 threads. Block = (bh, 16-row group). Thread: row i_local =
// tid>>3 (16 rows), j-slice jq = tid&7 (8 cols), S[8] state regs.
// cp.async double-buffers chunks of 8 timesteps of r/v/w/k into shared.
// ---------------------------------------------------------------------------
#define WCH 8                     // timesteps per chunk
#define NCHUNK (T_ / WCH)         // 256
// smem float offsets
#define RB_OFF 0                  // r: 2 bufs x 8 steps x 64
#define VB_OFF 1024
#define WB_OFF 2048               // w: 2 bufs x 8 steps x 16
#define KB_OFF 2304
#define WKV_SMEM_FLOATS 2560

__global__ __launch_bounds__(128) void wkv_kernel(
    const float* __restrict__ R, const float* __restrict__ Wd,
    const float* __restrict__ K, const float* __restrict__ V, float* __restrict__ Y)
{
    __shared__ float sm[WKV_SMEM_FLOATS];

    const int bh = blockIdx.x >> 2;        // 0..31
    const int rg = blockIdx.x & 3;         // 16-row group
    const int b  = bh >> 4;
    const int h  = bh & 15;
    const int tid = threadIdx.x;
    const int il  = tid >> 3;              // local row 0..15
    const int jq  = tid & 7;               // j-slice (8 cols)
    const int i   = rg * 16 + il;          // head-local row
    const size_t base = ((size_t)b * T_) * C_ + (size_t)h * NH;

    const uint32_t smb = smem_u32(sm);

    auto load_chunk = [&](int buf, int c) {
        int t0 = c * WCH;
        // r, v: 8 steps x 64 floats = 128 x 16B each -> 1 per thread
        int s   = tid >> 4;
        int seg = tid & 15;
        const float* rs = R + base + (size_t)(t0 + s) * C_ + seg * 4;
        const float* vs = V + base + (size_t)(t0 + s) * C_ + seg * 4;
        cp_async16(smb + (RB_OFF + buf * 512 + s * 64 + seg * 4) * 4, rs);
        cp_async16(smb + (VB_OFF + buf * 512 + s * 64 + seg * 4) * 4, vs);
        // w: threads 0..31, k: threads 32..63 (8 steps x 16 floats = 32 x 16B)
        if (tid < 32) {
            int s2 = tid >> 2, seg2 = tid & 3;
            cp_async16(smb + (WB_OFF + buf * 128 + s2 * 16 + seg2 * 4) * 4,
                       Wd + base + (size_t)(t0 + s2) * C_ + rg * 16 + seg2 * 4);
        } else if (tid < 64) {
            int t2 = tid - 32;
            int s2 = t2 >> 2, seg2 = t2 & 3;
            cp_async16(smb + (KB_OFF + buf * 128 + s2 * 16 + seg2 * 4) * 4,
                       K + base + (size_t)(t0 + s2) * C_ + rg * 16 + seg2 * 4);
        }
        cp_commit();
    };

    float S[8];
#pragma unroll
    for (int u = 0; u < 8; u++) S[u] = 0.0f;

    load_chunk(0, 0);
    load_chunk(1, 1);

    for (int c = 0; c < NCHUNK; c++) {
        const int buf = c & 1;
        if (c + 1 < NCHUNK) cp_wait<1>(); else cp_wait<0>();
        __syncthreads();

        const float* rb = sm + RB_OFF + buf * 512;
        const float* vb = sm + VB_OFF + buf * 512;
        const float* wb = sm + WB_OFF + buf * 128;
        const float* kb = sm + KB_OFF + buf * 128;

#pragma unroll
        for (int s = 0; s < WCH; s++) {
            float4 r0 = *reinterpret_cast<const float4*>(rb + s * 64 + jq * 8);
            float4 r1 = *reinterpret_cast<const float4*>(rb + s * 64 + jq * 8 + 4);
            float4 v0 = *reinterpret_cast<const float4*>(vb + s * 64 + jq * 8);
            float4 v1 = *reinterpret_cast<const float4*>(vb + s * 64 + jq * 8 + 4);
            const float wi = wb[s * 16 + il];
            const float ki = kb[s * 16 + il];

            float a0 = 0.f, a1 = 0.f;
            float t0v = S[0] * wi + ki * v0.x; S[0] = t0v; a0 += t0v * r0.x;
            float t1v = S[1] * wi + ki * v0.y; S[1] = t1v; a1 += t1v * r0.y;
            float t2v = S[2] * wi + ki * v0.z; S[2] = t2v; a0 += t2v * r0.z;
            float t3v = S[3] * wi + ki * v0.w; S[3] = t3v; a1 += t3v * r0.w;
            float t4v = S[4] * wi + ki * v1.x; S[4] = t4v; a0 += t4v * r1.x;
            float t5v = S[5] * wi + ki * v1.y; S[5] = t5v; a1 += t5v * r1.y;
            float t6v = S[6] * wi + ki * v1.z; S[6] = t6v; a0 += t6v * r1.z;
            float t7v = S[7] * wi + ki * v1.w; S[7] = t7v; a1 += t7v * r1.w;

            float red = a0 + a1;
            red += __shfl_xor_sync(0xffffffffu, red, 1);
            red += __shfl_xor_sync(0xffffffffu, red, 2);
            red += __shfl_xor_sync(0xffffffffu, red, 4);
            if (jq == 0) Y[base + (size_t)(c * WCH + s) * C_ + i] = red;
        }

        __syncthreads();
        if (c + 2 < NCHUNK) load_chunk(buf, c + 2);
        else cp_commit();
    }
}

// ---------------------------------------------------------------------------
// K7: LayerNorm(C) + rkv residual + gate:  z = (LN(y) + rkv) * g   (tf32 out)
// ---------------------------------------------------------------------------
__global__ __launch_bounds__(256) void ln_gate_kernel(
    const float* __restrict__ Yb, const float* __restrict__ Rb, const float* __restrict__ Kb,
    const float* __restrict__ Vb, const float* __restrict__ Gb,
    const float* __restrict__ rk, const float* __restrict__ lng, const float* __restrict__ lnb,
    float* __restrict__ Zb)
{
    const int m = blockIdx.x;
    const size_t base = (size_t)m * C_;
    __shared__ float sprod[C_];
    __shared__ float hdot[H_];
    __shared__ float rs[8], rq[8], stats[2];

    const int tid = threadIdx.x;
    float yv[4];
    float lsum = 0.f, lsq = 0.f;
#pragma unroll
    for (int u = 0; u < 4; u++) {
        int c = tid + u * 256;
        float t = Yb[base + c];
        yv[u] = t; lsum += t; lsq += t * t;
        sprod[c] = Rb[base + c] * Kb[base + c] * rk[c];
    }
#pragma unroll
    for (int o = 16; o > 0; o >>= 1) {
        lsum += __shfl_xor_sync(0xffffffffu, lsum, o);
        lsq  += __shfl_xor_sync(0xffffffffu, lsq,  o);
    }
    if ((tid & 31) == 0) { rs[tid >> 5] = lsum; rq[tid >> 5] = lsq; }
    __syncthreads();
    if (tid == 0) {
        float s = 0.f, q = 0.f;
        for (int wq = 0; wq < 8; wq++) { s += rs[wq]; q += rq[wq]; }
        float mu = s / (float)C_;
        stats[0] = mu;
        stats[1] = rsqrtf(q / (float)C_ - mu * mu + 1e-5f);
    }
    if (tid < 16) {
        float d = 0.f;
        for (int n = 0; n < 64; n++) d += sprod[tid * 64 + n];
        hdot[tid] = d;
    }
    __syncthreads();
    const float mu = stats[0], rstd = stats[1];
#pragma unroll
    for (int u = 0; u < 4; u++) {
        int c = tid + u * 256;
        int hh = c >> 6;
        float z = ((yv[u] - mu) * rstd * lng[c] + lnb[c] + hdot[hh] * Vb[base + c]) * Gb[base + c];
        Zb[base + c] = rtf(z);
    }
}

// ---------------------------------------------------------------------------
// Launcher
// ---------------------------------------------------------------------------
extern "C" void kernel_launch(void* const* d_in, const int* in_sizes, int n_in,
                              void* d_out, int out_size)
{
    (void)in_sizes; (void)n_in; (void)out_size;
    const float* x       = (const float*)d_in[0];
    const float* v_first = (const float*)d_in[1];
    const float* Wr  = (const float*)d_in[2];
    const float* Wk  = (const float*)d_in[3];
    const float* Wv  = (const float*)d_in[4];
    const float* Wo  = (const float*)d_in[5];
    const float* Wg1 = (const float*)d_in[6];
    const float* Wg2 = (const float*)d_in[7];
    const float* W1  = (const float*)d_in[8];
    const float* W2  = (const float*)d_in[9];
    const float* A1  = (const float*)d_in[10];
    const float* A2  = (const float*)d_in[11];
    const float* V1  = (const float*)d_in[12];
    const float* V2  = (const float*)d_in[13];
    const float* tm_r = (const float*)d_in[14];
    const float* tm_w = (const float*)d_in[15];
    const float* tm_k = (const float*)d_in[16];
    const float* tm_v = (const float*)d_in[17];
    const float* tm_a = (const float*)d_in[18];
    const float* tm_g = (const float*)d_in[19];
    const float* w0  = (const float*)d_in[20];
    const float* a0  = (const float*)d_in[21];
    const float* v0  = (const float*)d_in[22];
    const float* k_a = (const float*)d_in[24];
    const float* r_k = (const float*)d_in[25];
    const float* ln_g = (const float*)d_in[26];
    const float* ln_b = (const float*)d_in[27];

    float* buf = nullptr;
    cudaGetSymbolAddress((void**)&buf, g_scratch);
    auto S  = [&](int s) { return buf + (size_t)s * SLOT; };
    float* wbase = buf + 19 * SLOT;
    auto WB = [&](int w) { return (const float*)(wbase + (size_t)w * WSLOT); };

    cudaFuncSetAttribute((const void*)gemm_mma_kernel,
                         cudaFuncAttributeMaxDynamicSharedMemorySize, GEMM_SMEM);

    const int EW_BLOCKS = MROWS * C_ / 4 / 256;   // 4096
    dim3 gg(C_ / BNG, MROWS / BMG);               // (8, 32)

    // K0: tf32-round the weights
    Ptr12 ws;
    ws.p[0] = Wr;  ws.p[1] = Wk;  ws.p[2] = Wv;  ws.p[3] = W1;
    ws.p[4] = A1;  ws.p[5] = V1;  ws.p[6] = Wg1; ws.p[7] = W2;
    ws.p[8] = A2;  ws.p[9] = V2;  ws.p[10] = Wg2; ws.p[11] = Wo;
    wcvt_kernel<<<dim3(1024, 12), 256>>>(ws, wbase);

    // K1: token-shift mixes -> slots 0..5, tf32-rounded
    mix_kernel<<<EW_BLOCKS, 256>>>(x, tm_r, tm_w, tm_k, tm_v, tm_a, tm_g, buf);

    // Stage-1 batched GEMMs (7)
    GemmBatch7 b1;
    b1.it[0] = { S(0), WB(0), S(6),  0 };   // r
    b1.it[1] = { S(2), WB(1), S(7),  0 };   // k
    b1.it[2] = { S(3), WB(2), S(8),  0 };   // v
    b1.it[3] = { S(1), WB(3), S(9),  1 };   // w1 = tanh(.)
    b1.it[4] = { S(4), WB(4), S(10), 3 };   // a1
    b1.it[5] = { S(3), WB(5), S(11), 3 };   // v1
    b1.it[6] = { S(5), WB(6), S(12), 2 };   // g1 = sigmoid(.)
    gemm_mma_kernel<<<dim3(gg.x, gg.y, 7), 128, GEMM_SMEM>>>(b1);

    // Stage-2 batched GEMMs (4)
    GemmBatch7 b2;
    b2.it[0] = { S(9),  WB(7),  S(13), 0 };
    b2.it[1] = { S(10), WB(8),  S(14), 0 };
    b2.it[2] = { S(11), WB(9),  S(15), 0 };
    b2.it[3] = { S(12), WB(10), S(16), 0 };
    gemm_mma_kernel<<<dim3(gg.x, gg.y, 4), 128, GEMM_SMEM>>>(b2);

    // K5: w decay, k adjust, v blend
    ew2_kernel<<<EW_BLOCKS, 256>>>(S(13), S(14), S(15), S(7), S(8), v_first,
                                   w0, a0, v0, k_a);

    // K6: WKV scan -> y
    wkv_kernel<<<128, 128>>>(S(6), S(13), S(7), S(8), S(17));

    // K7: LN + rkv + gate -> z, tf32-rounded
    ln_gate_kernel<<<MROWS, 256>>>(S(17), S(6), S(7), S(8), S(16),
                                   r_k, ln_g, ln_b, S(18));

    // Final GEMM: out = z @ Wo^T
    GemmBatch7 b3;
    b3.it[0] = { S(18), WB(11), (float*)d_out, 0 };
    gemm_mma_kernel<<<dim3(gg.x, gg.y, 1), 128, GEMM_SMEM>>>(b3);
}

// round 7
// speedup vs baseline: 2.2496x; 1.0738x over previous
#include <cuda_runtime.h>
#include <cuda_bf16.h>
#include <cstdint>
#include <cstddef>

// Problem dims
#define B_    2
#define T_    2048
#define C_    1024
#define H_    16
#define NH    64
#define MROWS 4096                       // B*T
constexpr size_t SLOT = (size_t)MROWS * C_;   // 4,194,304 elements per scratch slot
constexpr size_t WSLOT = (size_t)C_ * C_;     // 1,048,576 elements per weight

// Scratch slots:
// 0:xr 1:xw 2:xk 3:xv 4:xa 5:xg
// 6:r 7:k 8:v 9:w1(tanh'd) 10:a1 11:v1 12:g1(sigmoid'd)
// 13:w(decayed) 14:(unused) 15:(unused) 16:g 17:y 18:z
// then 12 tf32-rounded weight copies
__device__ float g_scratch[19ull * 4194304ull + 12ull * 1048576ull];

__device__ __forceinline__ float sigm(float x) { return 1.0f / (1.0f + expf(-x)); }
__device__ __forceinline__ float rtf(float x) {
    float r; asm("cvt.rna.tf32.f32 %0, %1;" : "=f"(r) : "f"(x)); return r;
}
__device__ __forceinline__ float4 rtf4(float4 v) {
    return make_float4(rtf(v.x), rtf(v.y), rtf(v.z), rtf(v.w));
}

__device__ __forceinline__ uint32_t smem_u32(const void* p) {
    uint32_t a;
    asm("{ .reg .u64 t; cvta.to.shared.u64 t, %1; cvt.u32.u64 %0, t; }" : "=r"(a) : "l"(p));
    return a;
}
__device__ __forceinline__ void cp_async16(uint32_t s, const void* g) {
    asm volatile("cp.async.ca.shared.global [%0], [%1], 16;\n" :: "r"(s), "l"(g));
}
__device__ __forceinline__ void cp_commit() { asm volatile("cp.async.commit_group;\n"); }
template <int Nn> __device__ __forceinline__ void cp_wait() {
    asm volatile("cp.async.wait_group %0;\n" :: "n"(Nn));
}

// ---------------------------------------------------------------------------
// K0: one-time tf32 rounding of the 12 weight matrices
// ---------------------------------------------------------------------------
struct Ptr12 { const float* p[12]; };

__global__ __launch_bounds__(256) void wcvt_kernel(Ptr12 ws, float* __restrict__ out)
{
    int w  = blockIdx.y;
    int e4 = blockIdx.x * 256 + threadIdx.x;   // 0..262143
    float4 v = reinterpret_cast<const float4*>(ws.p[w])[e4];
    reinterpret_cast<float4*>(out + (size_t)w * WSLOT)[e4] = rtf4(v);
}

// ---------------------------------------------------------------------------
// K1: token-shift mixing — 6 tf32-rounded outputs from one pass over x
// ---------------------------------------------------------------------------
__global__ __launch_bounds__(256) void mix_kernel(
    const float* __restrict__ X,
    const float* __restrict__ tmr, const float* __restrict__ tmw,
    const float* __restrict__ tmk, const float* __restrict__ tmv,
    const float* __restrict__ tma, const float* __restrict__ tmg,
    float* __restrict__ buf)
{
    const int NC4 = C_ / 4;
    int e4 = blockIdx.x * 256 + threadIdx.x;
    if (e4 >= MROWS * NC4) return;
    int m  = e4 / NC4;
    int c4 = e4 - m * NC4;
    int t  = m & (T_ - 1);

    const float4* X4 = reinterpret_cast<const float4*>(X);
    float4 xc = X4[e4];
    float4 xp = make_float4(0.f, 0.f, 0.f, 0.f);
    if (t != 0) xp = X4[e4 - NC4];
    float4 xx = make_float4(xp.x - xc.x, xp.y - xc.y, xp.z - xc.z, xp.w - xc.w);

    float4* out = reinterpret_cast<float4*>(buf);
    const float* tms[6] = {tmr, tmw, tmk, tmv, tma, tmg};
#pragma unroll
    for (int s = 0; s < 6; s++) {
        float4 tm = reinterpret_cast<const float4*>(tms[s])[c4];
        float4 o = make_float4(xc.x + xx.x * tm.x, xc.y + xx.y * tm.y,
                               xc.z + xx.z * tm.z, xc.w + xx.w * tm.w);
        out[(size_t)s * (SLOT / 4) + e4] = rtf4(o);
    }
}

// ---------------------------------------------------------------------------
// K2: hand-rolled TF32 mma GEMM   out[m,n] = sum_k A[m,k] * W[n,k]
// BM=BN=128, BK=32, 2-stage cp.async, 4 warps (2M x 2N), warp tile 64x64,
// register double-buffered fragments (R5-proven config).
// Epilogue act: 0 none, 1 tanh+round, 2 sigmoid+round, 3 round,
//               4 w-decay(aux1=w0), 5 k-adjust rmw(aux1=a0,aux2=k_a),
//               6 v-blend rmw(aux1=v0,aux2=v_first)
// ---------------------------------------------------------------------------
#define BMG 128
#define BNG 128
#define BKG 32
#define NKT (C_ / BKG)        // 32
#define RS  36                // padded row stride in floats (32 + 4)
#define AST (128 * RS)        // floats per matrix tile per stage (4608)
#define STF (2 * AST)         // floats per stage (9216)
constexpr int GEMM_SMEM = 2 * STF * 4;   // 73728 bytes

struct GemmItem {
    const float* A; const float* W; float* O; int act;
    const float* aux1; const float* aux2;
};
struct GemmBatch7 { GemmItem it[7]; };

#define MMA_TF32(d, a, b) \
    asm volatile( \
        "mma.sync.aligned.m16n8k8.row.col.f32.tf32.tf32.f32 " \
        "{%0,%1,%2,%3}, {%4,%5,%6,%7}, {%8,%9}, {%0,%1,%2,%3};" \
        : "+f"((d)[0]), "+f"((d)[1]), "+f"((d)[2]), "+f"((d)[3]) \
        : "r"((a)[0]), "r"((a)[1]), "r"((a)[2]), "r"((a)[3]), \
          "r"((b)[0]), "r"((b)[1]))

extern __shared__ float smg[];

__global__ __launch_bounds__(128, 2) void gemm_mma_kernel(GemmBatch7 bt)
{
    const GemmItem gi = bt.it[blockIdx.z];
    const int tid  = threadIdx.x;
    const int lane = tid & 31;
    const int warpId = tid >> 5;
    const int wm = warpId & 1;            // 2 warps along M
    const int wn = warpId >> 1;           // 2 warps along N
    const int rw = wm * 64, cw = wn * 64;
    const int gid = lane >> 2;            // groupID 0..7
    const int tig = lane & 3;             // thread-in-group 0..3

    const int bm = blockIdx.y, bn = blockIdx.x;
    const float* Ab = gi.A + (size_t)bm * BMG * C_;
    const float* Wb = gi.W + (size_t)bn * BNG * C_;

    const uint32_t smb = smem_u32(smg);
    const uint32_t* smU = reinterpret_cast<const uint32_t*>(smg);

    auto load_stage = [&](int s, int kt) {
        uint32_t sb = smb + s * (STF * 4);
        int k0 = kt * BKG;
#pragma unroll
        for (int i = 0; i < 8; i++) {
            int f = tid + i * 128;        // 0..1023
            int row = f >> 3;
            int ch  = f & 7;
            cp_async16(sb + row * (RS * 4) + ch * 16,
                       Ab + (size_t)row * C_ + k0 + ch * 4);
            cp_async16(sb + AST * 4 + row * (RS * 4) + ch * 16,
                       Wb + (size_t)row * C_ + k0 + ch * 4);
        }
        cp_commit();
    };

    float acc[32][4];
#pragma unroll
    for (int i = 0; i < 32; i++)
#pragma unroll
        for (int j = 0; j < 4; j++) acc[i][j] = 0.0f;

    uint32_t af[2][16], bf[2][16];

    load_stage(0, 0);
    load_stage(1, 1);

    for (int kt = 0; kt < NKT; kt++) {
        const int s = kt & 1;
        if (kt + 1 < NKT) cp_wait<1>(); else cp_wait<0>();
        __syncthreads();

        const int sbase = s * STF;
        const int aoff = sbase + (rw + gid) * RS + tig;
        const int boff = sbase + AST + (cw + gid) * RS + tig;

        auto ldA = [&](int buf, int kk) {
#pragma unroll
            for (int mt = 0; mt < 4; mt++) {
                int base = aoff + mt * (16 * RS) + kk * 8;
                af[buf][mt*4+0] = smU[base];
                af[buf][mt*4+1] = smU[base + 8 * RS];
                af[buf][mt*4+2] = smU[base + 4];
                af[buf][mt*4+3] = smU[base + 8 * RS + 4];
            }
        };
        auto ldB = [&](int buf, int kk) {
#pragma unroll
            for (int nt = 0; nt < 8; nt++) {
                int base = boff + nt * (8 * RS) + kk * 8;
                bf[buf][nt*2+0] = smU[base];
                bf[buf][nt*2+1] = smU[base + 4];
            }
        };

        ldA(0, 0); ldB(0, 0);
        int pb = 0;
#pragma unroll
        for (int kk = 0; kk < 4; kk++) {
            if (kk < 3) { ldA(pb ^ 1, kk + 1); ldB(pb ^ 1, kk + 1); }
#pragma unroll
            for (int mt = 0; mt < 4; mt++)
#pragma unroll
                for (int nt = 0; nt < 8; nt++)
                    MMA_TF32(acc[mt*8+nt], af[pb] + mt*4, bf[pb] + nt*2);
            pb ^= 1;
        }

        __syncthreads();                 // all warps done reading stage s
        if (kt + 2 < NKT) load_stage(s, kt + 2);
    }

    // Epilogue
    const int act = gi.act;
    float* O = gi.O;
    const float* aux1 = gi.aux1;
    const float* aux2 = gi.aux2;
#pragma unroll
    for (int mt = 0; mt < 4; mt++) {
        int r0 = bm * BMG + rw + mt * 16 + gid;
#pragma unroll
        for (int nt = 0; nt < 8; nt++) {
            int col = bn * BNG + cw + nt * 8 + tig * 2;
            float v0 = acc[mt*8+nt][0], v1 = acc[mt*8+nt][1];
            float v2 = acc[mt*8+nt][2], v3 = acc[mt*8+nt][3];
            float* p0 = O + (size_t)r0 * C_ + col;
            float* p1 = O + (size_t)(r0 + 8) * C_ + col;
            if (act == 1) {
                v0 = rtf(tanhf(v0)); v1 = rtf(tanhf(v1));
                v2 = rtf(tanhf(v2)); v3 = rtf(tanhf(v3));
            } else if (act == 2) {
                v0 = rtf(sigm(v0)); v1 = rtf(sigm(v1));
                v2 = rtf(sigm(v2)); v3 = rtf(sigm(v3));
            } else if (act == 3) {
                v0 = rtf(v0); v1 = rtf(v1); v2 = rtf(v2); v3 = rtf(v3);
            } else if (act == 4) {
                // w = exp(-0.606531 * sigmoid(w0 + raw))
                float c0 = aux1[col], c1 = aux1[col + 1];
                v0 = expf(-0.606531f * sigm(c0 + v0));
                v1 = expf(-0.606531f * sigm(c1 + v1));
                v2 = expf(-0.606531f * sigm(c0 + v2));
                v3 = expf(-0.606531f * sigm(c1 + v3));
            } else if (act == 5) {
                // k *= 1 + (sigmoid(a0 + raw) - 1) * k_a   (rmw on O)
                float c0 = aux1[col], c1 = aux1[col + 1];
                float ka0 = aux2[col], ka1 = aux2[col + 1];
                float2 k0v = *reinterpret_cast<float2*>(p0);
                float2 k1v = *reinterpret_cast<float2*>(p1);
                v0 = k0v.x * (1.0f + (sigm(c0 + v0) - 1.0f) * ka0);
                v1 = k0v.y * (1.0f + (sigm(c1 + v1) - 1.0f) * ka1);
                v2 = k1v.x * (1.0f + (sigm(c0 + v2) - 1.0f) * ka0);
                v3 = k1v.y * (1.0f + (sigm(c1 + v3) - 1.0f) * ka1);
            } else if (act == 6) {
                // v += (v_first - v) * sigmoid(v0c + raw)   (rmw on O)
                float c0 = aux1[col], c1 = aux1[col + 1];
                const float* q0 = aux2 + (size_t)r0 * C_ + col;
                const float* q1 = aux2 + (size_t)(r0 + 8) * C_ + col;
                float2 vv0 = *reinterpret_cast<float2*>(p0);
                float2 vv1 = *reinterpret_cast<float2*>(p1);
                float2 vf0 = *reinterpret_cast<const float2*>(q0);
                float2 vf1 = *reinterpret_cast<const float2*>(q1);
                v0 = vv0.x + (vf0.x - vv0.x) * sigm(c0 + v0);
                v1 = vv0.y + (vf0.y - vv0.y) * sigm(c1 + v1);
                v2 = vv1.x + (vf1.x - vv1.x) * sigm(c0 + v2);
                v3 = vv1.y + (vf1.y - vv1.y) * sigm(c1 + v3);
            }
            *reinterpret_cast<float2*>(p0) = make_float2(v0, v1);
            *reinterpret_cast<float2*>(p1) = make_float2(v2, v3);
        }
    }
}

// ---------------------------------------------------------------------------
// K6: WKV-7 scan — smem-chunked (R6-proven).
// ---------------------------------------------------------------------------
#define WCH 8                     // timesteps per chunk
#define NCHUNK (T_ / WCH)         // 256
#define RB_OFF 0
#define VB_OFF 1024
#define WB_OFF 2048
#define KB_OFF 2304
#define WKV_SMEM_FLOATS 2560

__global__ __launch_bounds__(128) void wkv_kernel(
    const float* __restrict__ R, const float* __restrict__ Wd,
    const float* __restrict__ K, const float* __restrict__ V, float* __restrict__ Y)
{
    __shared__ float sm[WKV_SMEM_FLOATS];

    const int bh = blockIdx.x >> 2;        // 0..31
    const int rg = blockIdx.x & 3;         // 16-row group
    const int b  = bh >> 4;
    const int h  = bh & 15;
    const int tid = threadIdx.x;
    const int il  = tid >> 3;              // local row 0..15
    const int jq  = tid & 7;               // j-slice (8 cols)
    const int i   = rg * 16 + il;          // head-local row
    const size_t base = ((size_t)b * T_) * C_ + (size_t)h * NH;

    const uint32_t smb = smem_u32(sm);

    auto load_chunk = [&](int buf, int c) {
        int t0 = c * WCH;
        int s   = tid >> 4;
        int seg = tid & 15;
        const float* rs = R + base + (size_t)(t0 + s) * C_ + seg * 4;
        const float* vs = V + base + (size_t)(t0 + s) * C_ + seg * 4;
        cp_async16(smb + (RB_OFF + buf * 512 + s * 64 + seg * 4) * 4, rs);
        cp_async16(smb + (VB_OFF + buf * 512 + s * 64 + seg * 4) * 4, vs);
        if (tid < 32) {
            int s2 = tid >> 2, seg2 = tid & 3;
            cp_async16(smb + (WB_OFF + buf * 128 + s2 * 16 + seg2 * 4) * 4,
                       Wd + base + (size_t)(t0 + s2) * C_ + rg * 16 + seg2 * 4);
        } else if (tid < 64) {
            int t2 = tid - 32;
            int s2 = t2 >> 2, seg2 = t2 & 3;
            cp_async16(smb + (KB_OFF + buf * 128 + s2 * 16 + seg2 * 4) * 4,
                       K + base + (size_t)(t0 + s2) * C_ + rg * 16 + seg2 * 4);
        }
        cp_commit();
    };

    float S[8];
#pragma unroll
    for (int u = 0; u < 8; u++) S[u] = 0.0f;

    load_chunk(0, 0);
    load_chunk(1, 1);

    for (int c = 0; c < NCHUNK; c++) {
        const int buf = c & 1;
        if (c + 1 < NCHUNK) cp_wait<1>(); else cp_wait<0>();
        __syncthreads();

        const float* rb = sm + RB_OFF + buf * 512;
        const float* vb = sm + VB_OFF + buf * 512;
        const float* wb = sm + WB_OFF + buf * 128;
        const float* kb = sm + KB_OFF + buf * 128;

#pragma unroll
        for (int s = 0; s < WCH; s++) {
            float4 r0 = *reinterpret_cast<const float4*>(rb + s * 64 + jq * 8);
            float4 r1 = *reinterpret_cast<const float4*>(rb + s * 64 + jq * 8 + 4);
            float4 v0 = *reinterpret_cast<const float4*>(vb + s * 64 + jq * 8);
            float4 v1 = *reinterpret_cast<const float4*>(vb + s * 64 + jq * 8 + 4);
            const float wi = wb[s * 16 + il];
            const float ki = kb[s * 16 + il];

            float a0 = 0.f, a1 = 0.f;
            float t0v = S[0] * wi + ki * v0.x; S[0] = t0v; a0 += t0v * r0.x;
            float t1v = S[1] * wi + ki * v0.y; S[1] = t1v; a1 += t1v * r0.y;
            float t2v = S[2] * wi + ki * v0.z; S[2] = t2v; a0 += t2v * r0.z;
            float t3v = S[3] * wi + ki * v0.w; S[3] = t3v; a1 += t3v * r0.w;
            float t4v = S[4] * wi + ki * v1.x; S[4] = t4v; a0 += t4v * r1.x;
            float t5v = S[5] * wi + ki * v1.y; S[5] = t5v; a1 += t5v * r1.y;
            float t6v = S[6] * wi + ki * v1.z; S[6] = t6v; a0 += t6v * r1.z;
            float t7v = S[7] * wi + ki * v1.w; S[7] = t7v; a1 += t7v * r1.w;

            float red = a0 + a1;
            red += __shfl_xor_sync(0xffffffffu, red, 1);
            red += __shfl_xor_sync(0xffffffffu, red, 2);
            red += __shfl_xor_sync(0xffffffffu, red, 4);
            if (jq == 0) Y[base + (size_t)(c * WCH + s) * C_ + i] = red;
        }

        __syncthreads();
        if (c + 2 < NCHUNK) load_chunk(buf, c + 2);
        else cp_commit();
    }
}

// ---------------------------------------------------------------------------
// K7: LayerNorm(C) + rkv residual + gate:  z = (LN(y) + rkv) * g   (tf32 out)
// ---------------------------------------------------------------------------
__global__ __launch_bounds__(256) void ln_gate_kernel(
    const float* __restrict__ Yb, const float* __restrict__ Rb, const float* __restrict__ Kb,
    const float* __restrict__ Vb, const float* __restrict__ Gb,
    const float* __restrict__ rk, const float* __restrict__ lng, const float* __restrict__ lnb,
    float* __restrict__ Zb)
{
    const int m = blockIdx.x;
    const size_t base = (size_t)m * C_;
    __shared__ float sprod[C_];
    __shared__ float hdot[H_];
    __shared__ float rs[8], rq[8], stats[2];

    const int tid = threadIdx.x;
    float yv[4];
    float lsum = 0.f, lsq = 0.f;
#pragma unroll
    for (int u = 0; u < 4; u++) {
        int c = tid + u * 256;
        float t = Yb[base + c];
        yv[u] = t; lsum += t; lsq += t * t;
        sprod[c] = Rb[base + c] * Kb[base + c] * rk[c];
    }
#pragma unroll
    for (int o = 16; o > 0; o >>= 1) {
        lsum += __shfl_xor_sync(0xffffffffu, lsum, o);
        lsq  += __shfl_xor_sync(0xffffffffu, lsq,  o);
    }
    if ((tid & 31) == 0) { rs[tid >> 5] = lsum; rq[tid >> 5] = lsq; }
    __syncthreads();
    if (tid == 0) {
        float s = 0.f, q = 0.f;
        for (int wq = 0; wq < 8; wq++) { s += rs[wq]; q += rq[wq]; }
        float mu = s / (float)C_;
        stats[0] = mu;
        stats[1] = rsqrtf(q / (float)C_ - mu * mu + 1e-5f);
    }
    if (tid < 16) {
        float d = 0.f;
        for (int n = 0; n < 64; n++) d += sprod[tid * 64 + n];
        hdot[tid] = d;
    }
    __syncthreads();
    const float mu = stats[0], rstd = stats[1];
#pragma unroll
    for (int u = 0; u < 4; u++) {
        int c = tid + u * 256;
        int hh = c >> 6;
        float z = ((yv[u] - mu) * rstd * lng[c] + lnb[c] + hdot[hh] * Vb[base + c]) * Gb[base + c];
        Zb[base + c] = rtf(z);
    }
}

// ---------------------------------------------------------------------------
// Launcher
// ---------------------------------------------------------------------------
extern "C" void kernel_launch(void* const* d_in, const int* in_sizes, int n_in,
                              void* d_out, int out_size)
{
    (void)in_sizes; (void)n_in; (void)out_size;
    const float* x       = (const float*)d_in[0];
    const float* v_first = (const float*)d_in[1];
    const float* Wr  = (const float*)d_in[2];
    const float* Wk  = (const float*)d_in[3];
    const float* Wv  = (const float*)d_in[4];
    const float* Wo  = (const float*)d_in[5];
    const float* Wg1 = (const float*)d_in[6];
    const float* Wg2 = (const float*)d_in[7];
    const float* W1  = (const float*)d_in[8];
    const float* W2  = (const float*)d_in[9];
    const float* A1  = (const float*)d_in[10];
    const float* A2  = (const float*)d_in[11];
    const float* V1  = (const float*)d_in[12];
    const float* V2  = (const float*)d_in[13];
    const float* tm_r = (const float*)d_in[14];
    const float* tm_w = (const float*)d_in[15];
    const float* tm_k = (const float*)d_in[16];
    const float* tm_v = (const float*)d_in[17];
    const float* tm_a = (const float*)d_in[18];
    const float* tm_g = (const float*)d_in[19];
    const float* w0  = (const float*)d_in[20];
    const float* a0  = (const float*)d_in[21];
    const float* v0  = (const float*)d_in[22];
    const float* k_a = (const float*)d_in[24];
    const float* r_k = (const float*)d_in[25];
    const float* ln_g = (const float*)d_in[26];
    const float* ln_b = (const float*)d_in[27];

    float* buf = nullptr;
    cudaGetSymbolAddress((void**)&buf, g_scratch);
    auto S  = [&](int s) { return buf + (size_t)s * SLOT; };
    float* wbase = buf + 19 * SLOT;
    auto WB = [&](int w) { return (const float*)(wbase + (size_t)w * WSLOT); };

    cudaFuncSetAttribute((const void*)gemm_mma_kernel,
                         cudaFuncAttributeMaxDynamicSharedMemorySize, GEMM_SMEM);

    const int EW_BLOCKS = MROWS * C_ / 4 / 256;   // 4096
    dim3 gg(C_ / BNG, MROWS / BMG);               // (8, 32)

    // K0: tf32-round the weights
    Ptr12 ws;
    ws.p[0] = Wr;  ws.p[1] = Wk;  ws.p[2] = Wv;  ws.p[3] = W1;
    ws.p[4] = A1;  ws.p[5] = V1;  ws.p[6] = Wg1; ws.p[7] = W2;
    ws.p[8] = A2;  ws.p[9] = V2;  ws.p[10] = Wg2; ws.p[11] = Wo;
    wcvt_kernel<<<dim3(1024, 12), 256>>>(ws, wbase);

    // K1: token-shift mixes -> slots 0..5, tf32-rounded
    mix_kernel<<<EW_BLOCKS, 256>>>(x, tm_r, tm_w, tm_k, tm_v, tm_a, tm_g, buf);

    // Stage-1 batched GEMMs (7)
    GemmBatch7 b1;
    b1.it[0] = { S(0), WB(0), S(6),  0, nullptr, nullptr };   // r
    b1.it[1] = { S(2), WB(1), S(7),  0, nullptr, nullptr };   // k
    b1.it[2] = { S(3), WB(2), S(8),  0, nullptr, nullptr };   // v
    b1.it[3] = { S(1), WB(3), S(9),  1, nullptr, nullptr };   // w1 = tanh(.)
    b1.it[4] = { S(4), WB(4), S(10), 3, nullptr, nullptr };   // a1
    b1.it[5] = { S(3), WB(5), S(11), 3, nullptr, nullptr };   // v1
    b1.it[6] = { S(5), WB(6), S(12), 2, nullptr, nullptr };   // g1 = sigmoid(.)
    gemm_mma_kernel<<<dim3(gg.x, gg.y, 7), 128, GEMM_SMEM>>>(b1);

    // Stage-2 batched GEMMs (4) with fused ew2 epilogues
    GemmBatch7 b2;
    b2.it[0] = { S(9),  WB(7),  S(13), 4, w0,  nullptr };   // w = exp(-.6*sig(w0+.))
    b2.it[1] = { S(10), WB(8),  S(7),  5, a0,  k_a     };   // k-adjust (rmw k)
    b2.it[2] = { S(11), WB(9),  S(8),  6, v0,  v_first };   // v-blend (rmw v)
    b2.it[3] = { S(12), WB(10), S(16), 0, nullptr, nullptr }; // g
    gemm_mma_kernel<<<dim3(gg.x, gg.y, 4), 128, GEMM_SMEM>>>(b2);

    // K6: WKV scan -> y
    wkv_kernel<<<128, 128>>>(S(6), S(13), S(7), S(8), S(17));

    // K7: LN + rkv + gate -> z, tf32-rounded
    ln_gate_kernel<<<MROWS, 256>>>(S(17), S(6), S(7), S(8), S(16),
                                   r_k, ln_g, ln_b, S(18));

    // Final GEMM: out = z @ Wo^T
    GemmBatch7 b3;
    b3.it[0] = { S(18), WB(11), (float*)d_out, 0, nullptr, nullptr };
    gemm_mma_kernel<<<dim3(gg.x, gg.y, 1), 128, GEMM_SMEM>>>(b3);
}